// round 1
// baseline (speedup 1.0000x reference)
#include <cuda_runtime.h>
#include <cuda_bf16.h>
#include <math.h>

// Problem constants
constexpr int L = 4;
constexpr int C = 1024;
constexpr int F = 4096;
constexpr int V = 50304;
constexpr int B = 2;
constexpr int T = 1024;
constexpr int M = B * T;            // 2048 rows

// ---------------------------------------------------------------------------
// Scratch (static __device__ arrays; no allocations allowed)
// ---------------------------------------------------------------------------
__device__ float g_x   [M * C];     // residual stream
__device__ float g_xn  [M * C];     // layernorm output
__device__ float g_r   [M * C];     // sigmoid(xn@Wr) / FFN gate
__device__ float g_k   [M * C];
__device__ float g_v   [M * C];
__device__ float g_y   [M * C];     // wkv output
__device__ float g_kf  [M * F];     // FFN hidden
__device__ float g_sakv[M * C];     // wkv forward scan scratch (num)
__device__ float g_sak [M * C];     // wkv forward scan scratch (den)

// ---------------------------------------------------------------------------
// Embedding gather: x[row, :] = emb[idx[row], :]
// ---------------------------------------------------------------------------
__global__ void embed_k(const int* __restrict__ idx,
                        const float* __restrict__ emb,
                        float* __restrict__ x) {
    int row = blockIdx.x;
    int id = idx[row];
    const float4* src = (const float4*)(emb + (size_t)id * C);
    float4* dst = (float4*)(x + (size_t)row * C);
    for (int i = threadIdx.x; i < C / 4; i += blockDim.x) dst[i] = src[i];
}

// ---------------------------------------------------------------------------
// LayerNorm over last dim (C=1024). One block (256 threads) per row.
// ---------------------------------------------------------------------------
__global__ __launch_bounds__(256) void layernorm_k(const float* __restrict__ x,
                                                   const float* __restrict__ w,
                                                   const float* __restrict__ b,
                                                   float* __restrict__ out) {
    __shared__ float red[256];
    int row = blockIdx.x;
    const float* xr = x + (size_t)row * C;
    float v[4];
    float s = 0.f;
#pragma unroll
    for (int i = 0; i < 4; i++) { v[i] = xr[threadIdx.x + 256 * i]; s += v[i]; }
    red[threadIdx.x] = s;
    __syncthreads();
    for (int o = 128; o > 0; o >>= 1) {
        if (threadIdx.x < o) red[threadIdx.x] += red[threadIdx.x + o];
        __syncthreads();
    }
    float mu = red[0] * (1.f / C);
    __syncthreads();
    float s2 = 0.f;
#pragma unroll
    for (int i = 0; i < 4; i++) { float d = v[i] - mu; s2 += d * d; }
    red[threadIdx.x] = s2;
    __syncthreads();
    for (int o = 128; o > 0; o >>= 1) {
        if (threadIdx.x < o) red[threadIdx.x] += red[threadIdx.x + o];
        __syncthreads();
    }
    float rstd = rsqrtf(red[0] * (1.f / C) + 1e-5f);
#pragma unroll
    for (int i = 0; i < 4; i++) {
        int c = threadIdx.x + 256 * i;
        out[(size_t)row * C + c] = (v[i] - mu) * rstd * w[c] + b[c];
    }
}

// ---------------------------------------------------------------------------
// SGEMM: C[M,N] = epi( A[M,K] @ W[K,N] )
//   EPI 0: plain     1: sigmoid    2: relu^2
//   EPI 3: res + acc (residual add)
//   EPI 4: res + gate * acc (gated residual)
// Block tile 128x128, K-tile 8, 256 threads, 8x8 per-thread micro-tile.
// All dims assumed divisible (M=2048; N in {1024,4096,50304}; K in {1024,4096}).
// ---------------------------------------------------------------------------
constexpr int BM = 128, BN = 128, BK = 8, TM = 8, TN = 8;

template <int EPI>
__global__ __launch_bounds__(256) void sgemm_k(const float* __restrict__ A,
                                               const float* __restrict__ W,
                                               float* Cc,
                                               const float* res,
                                               const float* gate,
                                               int Mm, int Nn, int Kk) {
    __shared__ float As[BK][BM];
    __shared__ float Bs[BK][BN];

    int tid = threadIdx.x;
    int block_row = blockIdx.y * BM;
    int block_col = blockIdx.x * BN;

    int a_row = tid >> 1;            // 0..127
    int a_col = (tid & 1) * 4;       // 0 or 4
    int b_row = tid >> 5;            // 0..7
    int b_col = (tid & 31) * 4;      // 0..124

    int ty = tid >> 4;               // 0..15
    int tx = tid & 15;               // 0..15

    float acc[TM][TN];
#pragma unroll
    for (int i = 0; i < TM; i++)
#pragma unroll
        for (int j = 0; j < TN; j++) acc[i][j] = 0.f;

    const float* Aptr = A + (size_t)block_row * Kk;
    const float* Wptr = W + block_col;

    for (int k0 = 0; k0 < Kk; k0 += BK) {
        float4 av = *(const float4*)(Aptr + (size_t)a_row * Kk + k0 + a_col);
        As[a_col + 0][a_row] = av.x;
        As[a_col + 1][a_row] = av.y;
        As[a_col + 2][a_row] = av.z;
        As[a_col + 3][a_row] = av.w;
        float4 bv = *(const float4*)(Wptr + (size_t)(k0 + b_row) * Nn + b_col);
        *(float4*)&Bs[b_row][b_col] = bv;
        __syncthreads();
#pragma unroll
        for (int kk = 0; kk < BK; kk++) {
            float a[TM], bb[TN];
#pragma unroll
            for (int i = 0; i < TM; i++) a[i] = As[kk][ty * TM + i];
#pragma unroll
            for (int j = 0; j < TN; j++) bb[j] = Bs[kk][tx * TN + j];
#pragma unroll
            for (int i = 0; i < TM; i++)
#pragma unroll
                for (int j = 0; j < TN; j++) acc[i][j] += a[i] * bb[j];
        }
        __syncthreads();
    }

#pragma unroll
    for (int i = 0; i < TM; i++) {
        int row = block_row + ty * TM + i;
#pragma unroll
        for (int j = 0; j < TN; j += 4) {
            int col = block_col + tx * TN + j;
            size_t off = (size_t)row * Nn + col;
            float o0 = acc[i][j], o1 = acc[i][j + 1], o2 = acc[i][j + 2], o3 = acc[i][j + 3];
            if (EPI == 1) {
                o0 = 1.f / (1.f + expf(-o0));
                o1 = 1.f / (1.f + expf(-o1));
                o2 = 1.f / (1.f + expf(-o2));
                o3 = 1.f / (1.f + expf(-o3));
            } else if (EPI == 2) {
                o0 = fmaxf(o0, 0.f); o0 *= o0;
                o1 = fmaxf(o1, 0.f); o1 *= o1;
                o2 = fmaxf(o2, 0.f); o2 *= o2;
                o3 = fmaxf(o3, 0.f); o3 *= o3;
            } else if (EPI == 3) {
                float4 rv = *(const float4*)(res + off);
                o0 += rv.x; o1 += rv.y; o2 += rv.z; o3 += rv.w;
            } else if (EPI == 4) {
                float4 rv = *(const float4*)(res + off);
                float4 gv = *(const float4*)(gate + off);
                o0 = rv.x + gv.x * o0;
                o1 = rv.y + gv.y * o1;
                o2 = rv.z + gv.z * o2;
                o3 = rv.w + gv.w * o3;
            }
            float4 ov = make_float4(o0, o1, o2, o3);
            *(float4*)(Cc + off) = ov;
        }
    }
}

// ---------------------------------------------------------------------------
// Bidirectional WKV. One thread per (b, c): forward exclusive scan stores
// (akv_f, ak_f); backward pass combines and writes y.
// ---------------------------------------------------------------------------
__global__ __launch_bounds__(256) void wkv_k(const float* __restrict__ r,
                                             const float* __restrict__ k,
                                             const float* __restrict__ v,
                                             const float* __restrict__ w,
                                             const float* __restrict__ u,
                                             float* __restrict__ y,
                                             float* __restrict__ sakv,
                                             float* __restrict__ sak) {
    int gid = blockIdx.x * blockDim.x + threadIdx.x;   // 0 .. B*C-1
    int b = gid >> 10;          // / C
    int c = gid & (C - 1);
    float decay = expf(-expf(w[c]));
    float eu = expf(u[c]);
    size_t base = (size_t)b * T * C + c;

    float aA = 0.f, aB = 0.f;
#pragma unroll 4
    for (int t = 0; t < T; t++) {
        size_t o = base + (size_t)t * C;
        float ek = expf(k[o]);
        float kv = ek * v[o];
        sakv[o] = aA;
        sak[o]  = aB;
        aA = aA * decay + kv;
        aB = aB * decay + ek;
    }

    float bA = 0.f, bB = 0.f;
#pragma unroll 4
    for (int t = T - 1; t >= 0; t--) {
        size_t o = base + (size_t)t * C;
        float vv = v[o];
        float ek = expf(k[o]);
        float kv = ek * vv;
        float num = sakv[o] + bA + eu * vv;
        float den = sak[o]  + bB + eu;
        y[o] = r[o] * num / (den + 1e-8f);
        bA = bA * decay + kv;
        bB = bB * decay + ek;
    }
}

// ---------------------------------------------------------------------------
// Host launch
// ---------------------------------------------------------------------------
extern "C" void kernel_launch(void* const* d_in, const int* in_sizes, int n_in,
                              void* d_out, int out_size) {
    const int*   idx     = (const int*)  d_in[0];
    const float* emb     = (const float*)d_in[1];
    const float* ln1_w   = (const float*)d_in[2];
    const float* ln1_b   = (const float*)d_in[3];
    const float* Wr      = (const float*)d_in[4];
    const float* Wk      = (const float*)d_in[5];
    const float* Wv      = (const float*)d_in[6];
    const float* w_decay = (const float*)d_in[7];
    const float* u_bonus = (const float*)d_in[8];
    const float* Wo      = (const float*)d_in[9];
    const float* ln2_w   = (const float*)d_in[10];
    const float* ln2_b   = (const float*)d_in[11];
    const float* Wfk     = (const float*)d_in[12];
    const float* Wfv     = (const float*)d_in[13];
    const float* Wfr     = (const float*)d_in[14];
    const float* lnout_w = (const float*)d_in[15];
    const float* lnout_b = (const float*)d_in[16];
    const float* head_W  = (const float*)d_in[17];
    float* out = (float*)d_out;

    float *x, *xn, *r, *k, *v, *y, *kf, *sa, *sb;
    cudaGetSymbolAddress((void**)&x,  g_x);
    cudaGetSymbolAddress((void**)&xn, g_xn);
    cudaGetSymbolAddress((void**)&r,  g_r);
    cudaGetSymbolAddress((void**)&k,  g_k);
    cudaGetSymbolAddress((void**)&v,  g_v);
    cudaGetSymbolAddress((void**)&y,  g_y);
    cudaGetSymbolAddress((void**)&kf, g_kf);
    cudaGetSymbolAddress((void**)&sa, g_sakv);
    cudaGetSymbolAddress((void**)&sb, g_sak);

    embed_k<<<M, 256>>>(idx, emb, x);

    dim3 gCC(C / BN, M / BM);       // N=1024
    dim3 gCF(F / BN, M / BM);       // N=4096
    dim3 gCV(V / BN, M / BM);       // N=50304

    for (int l = 0; l < L; l++) {
        const float* l1w = ln1_w + (size_t)l * C;
        const float* l1b = ln1_b + (size_t)l * C;
        const float* wr  = Wr  + (size_t)l * C * C;
        const float* wk  = Wk  + (size_t)l * C * C;
        const float* wv  = Wv  + (size_t)l * C * C;
        const float* wd  = w_decay + (size_t)l * C;
        const float* ub  = u_bonus + (size_t)l * C;
        const float* wo  = Wo  + (size_t)l * C * C;
        const float* l2w = ln2_w + (size_t)l * C;
        const float* l2b = ln2_b + (size_t)l * C;
        const float* wfk = Wfk + (size_t)l * C * F;
        const float* wfv = Wfv + (size_t)l * F * C;
        const float* wfr = Wfr + (size_t)l * C * C;

        // time-mix
        layernorm_k<<<M, 256>>>(x, l1w, l1b, xn);
        sgemm_k<1><<<gCC, 256>>>(xn, wr, r, nullptr, nullptr, M, C, C);   // sigmoid
        sgemm_k<0><<<gCC, 256>>>(xn, wk, k, nullptr, nullptr, M, C, C);
        sgemm_k<0><<<gCC, 256>>>(xn, wv, v, nullptr, nullptr, M, C, C);
        wkv_k<<<(B * C) / 256, 256>>>(r, k, v, wd, ub, y, sa, sb);
        sgemm_k<3><<<gCC, 256>>>(y, wo, x, x, nullptr, M, C, C);          // x += y@Wo

        // channel-mix
        layernorm_k<<<M, 256>>>(x, l2w, l2b, xn);
        sgemm_k<1><<<gCC, 256>>>(xn, wfr, r, nullptr, nullptr, M, C, C);  // gate
        sgemm_k<2><<<gCF, 256>>>(xn, wfk, kf, nullptr, nullptr, M, F, C); // relu^2
        sgemm_k<4><<<gCC, 256>>>(kf, wfv, x, x, r, M, C, F);              // x += gate*(kf@Wfv)
    }

    layernorm_k<<<M, 256>>>(x, lnout_w, lnout_b, xn);
    sgemm_k<0><<<gCV, 256>>>(xn, head_W, out, nullptr, nullptr, M, V, C);
}

// round 3
// speedup vs baseline: 1.7661x; 1.7661x over previous
#include <cuda_runtime.h>
#include <cuda_bf16.h>
#include <cstdint>
#include <math.h>

// ---------------------------------------------------------------------------
// Problem constants
// ---------------------------------------------------------------------------
constexpr int L = 4;
constexpr int C = 1024;
constexpr int F = 4096;
constexpr int V = 50304;
constexpr int B = 2;
constexpr int T = 1024;
constexpr int M = B * T;            // 2048 rows

// ---------------------------------------------------------------------------
// Scratch (static __device__ arrays; 16B-aligned for cp.async / uint4)
// ---------------------------------------------------------------------------
constexpr size_t MB1 = size_t(C) * C;                 // 1,048,576
constexpr size_t WOFF_LAYER = 13 * MB1;               // 5*C*C + C*F + F*C
constexpr size_t WOFF_WR  = 0;
constexpr size_t WOFF_WK  = 1 * MB1;
constexpr size_t WOFF_WV  = 2 * MB1;
constexpr size_t WOFF_WO  = 3 * MB1;
constexpr size_t WOFF_WFR = 4 * MB1;
constexpr size_t WOFF_WFK = 5 * MB1;                  // [F, C]
constexpr size_t WOFF_WFV = 9 * MB1;                  // [C, F]
constexpr size_t WOFF_HEAD = size_t(L) * WOFF_LAYER;
constexpr size_t WTOTAL = WOFF_HEAD + size_t(V) * C;

__device__ alignas(16) __nv_bfloat16 g_wt_hi[WTOTAL];
__device__ alignas(16) __nv_bfloat16 g_wt_lo[WTOTAL];

__device__ alignas(16) float g_x   [size_t(M) * C];
__device__ alignas(16) float g_r   [size_t(M) * C];
__device__ alignas(16) float g_k   [size_t(M) * C];
__device__ alignas(16) float g_v   [size_t(M) * C];
__device__ alignas(16) float g_sakv[size_t(M) * C];
__device__ alignas(16) float g_sak [size_t(M) * C];
__device__ alignas(16) __nv_bfloat16 g_xn_hi[size_t(M) * C];
__device__ alignas(16) __nv_bfloat16 g_xn_lo[size_t(M) * C];
__device__ alignas(16) __nv_bfloat16 g_y_hi [size_t(M) * C];
__device__ alignas(16) __nv_bfloat16 g_y_lo [size_t(M) * C];
__device__ alignas(16) __nv_bfloat16 g_kf_hi[size_t(M) * F];
__device__ alignas(16) __nv_bfloat16 g_kf_lo[size_t(M) * F];

// ---------------------------------------------------------------------------
// Weight convert + transpose: W [K,N] fp32 -> out_hi/out_lo [N,K] bf16 split
// ---------------------------------------------------------------------------
__global__ __launch_bounds__(256) void convert_transpose_k(
    const float* __restrict__ W,
    __nv_bfloat16* __restrict__ out_hi,
    __nv_bfloat16* __restrict__ out_lo,
    int K, int N) {
    __shared__ float tile[32][33];
    int n0 = blockIdx.x * 32;
    int k0 = blockIdx.y * 32;
    int tx = threadIdx.x;          // 0..31
    int ty = threadIdx.y;          // 0..7
#pragma unroll
    for (int r = ty; r < 32; r += 8)
        tile[r][tx] = W[(size_t)(k0 + r) * N + n0 + tx];
    __syncthreads();
#pragma unroll
    for (int r = ty; r < 32; r += 8) {
        float val = tile[tx][r];   // W[k0+tx][n0+r]
        __nv_bfloat16 h = __float2bfloat16(val);
        float lo = val - __bfloat162float(h);
        size_t off = (size_t)(n0 + r) * K + k0 + tx;
        out_hi[off] = h;
        out_lo[off] = __float2bfloat16(lo);
    }
}

// ---------------------------------------------------------------------------
// Embedding gather
// ---------------------------------------------------------------------------
__global__ void embed_k(const int* __restrict__ idx,
                        const float* __restrict__ emb,
                        float* __restrict__ x) {
    int row = blockIdx.x;
    int id = idx[row];
    const float4* src = (const float4*)(emb + (size_t)id * C);
    float4* dst = (float4*)(x + (size_t)row * C);
    for (int i = threadIdx.x; i < C / 4; i += blockDim.x) dst[i] = src[i];
}

// ---------------------------------------------------------------------------
// LayerNorm -> split bf16 output
// ---------------------------------------------------------------------------
__global__ __launch_bounds__(256) void layernorm_k(const float* __restrict__ x,
                                                   const float* __restrict__ w,
                                                   const float* __restrict__ b,
                                                   __nv_bfloat16* __restrict__ out_hi,
                                                   __nv_bfloat16* __restrict__ out_lo) {
    __shared__ float red[256];
    int row = blockIdx.x;
    const float* xr = x + (size_t)row * C;
    float v[4];
    float s = 0.f;
#pragma unroll
    for (int i = 0; i < 4; i++) { v[i] = xr[threadIdx.x + 256 * i]; s += v[i]; }
    red[threadIdx.x] = s;
    __syncthreads();
    for (int o = 128; o > 0; o >>= 1) {
        if (threadIdx.x < o) red[threadIdx.x] += red[threadIdx.x + o];
        __syncthreads();
    }
    float mu = red[0] * (1.f / C);
    __syncthreads();
    float s2 = 0.f;
#pragma unroll
    for (int i = 0; i < 4; i++) { float d = v[i] - mu; s2 += d * d; }
    red[threadIdx.x] = s2;
    __syncthreads();
    for (int o = 128; o > 0; o >>= 1) {
        if (threadIdx.x < o) red[threadIdx.x] += red[threadIdx.x + o];
        __syncthreads();
    }
    float rstd = rsqrtf(red[0] * (1.f / C) + 1e-5f);
#pragma unroll
    for (int i = 0; i < 4; i++) {
        int c = threadIdx.x + 256 * i;
        float o = (v[i] - mu) * rstd * w[c] + b[c];
        __nv_bfloat16 h = __float2bfloat16(o);
        size_t off = (size_t)row * C + c;
        out_hi[off] = h;
        out_lo[off] = __float2bfloat16(o - __bfloat162float(h));
    }
}

// ---------------------------------------------------------------------------
// Split-bf16 tensor-core GEMM via mma.sync (non-'a' PTX; works on sm_103).
//   out = epi( A[M,K] @ Wt[N,K]^T ),  3 MMA terms: Ah*Bh + Ah*Bl + Al*Bh.
//   EPI 0 plain fp32 | 1 sigmoid fp32 | 2 relu^2 -> bf16 hi/lo
//   EPI 3 res + acc  | 4 res + gate * acc
// CTA 128x128, BK=32, 8 warps (2x4), warp tile 64x32 (4x4 of m16n8k16).
// 3-stage cp.async pipeline; smem rows padded to 40 elems (80B stride).
// ---------------------------------------------------------------------------
constexpr int BK = 32;
constexpr int SSTRIDE = 40;                       // padded elems per smem row
constexpr int TILEB  = 128 * SSTRIDE * 2;         // 10240 B per tile
constexpr int STAGEB = 4 * TILEB;                 // Ah, Al, Bh, Bl
constexpr int NSTAGE = 3;
constexpr int GEMM_SMEM = NSTAGE * STAGEB;        // 122880 B

__device__ __forceinline__ uint32_t smem_u32(const void* p) {
    uint32_t a;
    asm("{ .reg .u64 t; cvta.to.shared.u64 t, %1; cvt.u32.u64 %0, t; }"
        : "=r"(a) : "l"(p));
    return a;
}

__device__ __forceinline__ void ldsm_x4(uint32_t addr, uint32_t& r0, uint32_t& r1,
                                        uint32_t& r2, uint32_t& r3) {
    asm volatile("ldmatrix.sync.aligned.m8n8.x4.shared.b16 {%0,%1,%2,%3}, [%4];"
                 : "=r"(r0), "=r"(r1), "=r"(r2), "=r"(r3) : "r"(addr));
}

__device__ __forceinline__ void mma_bf16(float* d, const uint32_t* a,
                                         uint32_t b0, uint32_t b1) {
    asm volatile(
        "mma.sync.aligned.m16n8k16.row.col.f32.bf16.bf16.f32 "
        "{%0,%1,%2,%3}, {%4,%5,%6,%7}, {%8,%9}, {%0,%1,%2,%3};"
        : "+f"(d[0]), "+f"(d[1]), "+f"(d[2]), "+f"(d[3])
        : "r"(a[0]), "r"(a[1]), "r"(a[2]), "r"(a[3]), "r"(b0), "r"(b1));
}

__device__ __forceinline__ void cp16(uint32_t sp, const void* gp) {
    asm volatile("cp.async.cg.shared.global [%0], [%1], 16;" :: "r"(sp), "l"(gp));
}

// Each thread copies 2 rows x 4 x 16B of ONE tile (tile chosen by tid>>6).
__device__ __forceinline__ void issue_tile(uint32_t tile_base,
                                           const __nv_bfloat16* __restrict__ g,
                                           int row0, int Kdim, int k0, int t64) {
#pragma unroll
    for (int j = 0; j < 2; j++) {
        int r = t64 * 2 + j;
        const __nv_bfloat16* gp = g + (size_t)(row0 + r) * Kdim + k0;
        uint32_t sp = tile_base + r * (SSTRIDE * 2);
#pragma unroll
        for (int cc = 0; cc < 4; cc++)
            cp16(sp + cc * 16, gp + cc * 8);
    }
}

template <int EPI>
__global__ __launch_bounds__(256, 1) void gemm_mma(
    const __nv_bfloat16* __restrict__ Ah, const __nv_bfloat16* __restrict__ Al,
    const __nv_bfloat16* __restrict__ Bh, const __nv_bfloat16* __restrict__ Bl,
    float* __restrict__ Cc,
    __nv_bfloat16* __restrict__ Chi, __nv_bfloat16* __restrict__ Clo,
    const float* __restrict__ res, const float* __restrict__ gate,
    int N, int K) {
    extern __shared__ __align__(128) char sm[];
    uint32_t smem = smem_u32(sm);
    int tid = threadIdx.x;
    int wid = tid >> 5;
    int lane = tid & 31;
    int brow = blockIdx.x * 128;
    int bcol = blockIdx.y * 128;
    int warp_m = wid & 1;          // 0..1 (64 rows each)
    int warp_n = wid >> 1;         // 0..3 (32 cols each)

    // cp.async role for this thread
    int tile_id = tid >> 6;        // 0:Ah 1:Al 2:Bh 3:Bl
    int t64 = tid & 63;
    const __nv_bfloat16* gsrc = (tile_id == 0) ? Ah : (tile_id == 1) ? Al
                                : (tile_id == 2) ? Bh : Bl;
    int row0 = (tile_id < 2) ? brow : bcol;

    float acc[4][4][4];
#pragma unroll
    for (int i = 0; i < 4; i++)
#pragma unroll
        for (int j = 0; j < 4; j++)
#pragma unroll
            for (int q = 0; q < 4; q++) acc[i][j][q] = 0.f;

    int nch = K >> 5;              // BK = 32

    // prologue: stages 0, 1
#pragma unroll
    for (int s = 0; s < 2; s++) {
        issue_tile(smem + s * STAGEB + tile_id * TILEB, gsrc, row0, K, s * BK, t64);
        asm volatile("cp.async.commit_group;");
    }

    // ldmatrix lane address components (byte offsets within a tile)
    int a_r = (lane & 15);                    // row within 16-row block
    int a_k = ((lane >> 4) << 3);             // 0 or 8 (k offset)
    int b_g = lane >> 3;
    int b_r = ((b_g & 1) << 3) + (lane & 7);  // row within 16-row block
    int b_k = ((b_g >> 1) << 3);              // 0 or 8

    for (int c = 0; c < nch; c++) {
        asm volatile("cp.async.wait_group 1;");
        __syncthreads();
        if (c + 2 < nch) {
            int slot = (c + 2) % NSTAGE;
            issue_tile(smem + slot * STAGEB + tile_id * TILEB, gsrc, row0, K,
                       (c + 2) * BK, t64);
            asm volatile("cp.async.commit_group;");
        }

        uint32_t sbase = smem + (c % NSTAGE) * STAGEB;
#pragma unroll
        for (int ks = 0; ks < 2; ks++) {
            int kk = ks * 16;
            uint32_t ah[4][4], al[4][4], bh[4][2], bl[4][2];
            // A fragments (hi & lo), 4 m-tiles of 16
            uint32_t acol = (uint32_t)(kk + a_k) * 2;
#pragma unroll
            for (int mi = 0; mi < 4; mi++) {
                uint32_t ad = sbase + (warp_m * 64 + mi * 16 + a_r) * (SSTRIDE * 2) + acol;
                ldsm_x4(ad, ah[mi][0], ah[mi][1], ah[mi][2], ah[mi][3]);
                ldsm_x4(ad + TILEB, al[mi][0], al[mi][1], al[mi][2], al[mi][3]);
            }
            // B fragments (hi & lo): one x4 covers two 8-col n-tiles
            uint32_t bcolb = (uint32_t)(kk + b_k) * 2;
#pragma unroll
            for (int nj = 0; nj < 2; nj++) {
                uint32_t bd = sbase + 2 * TILEB +
                              (warp_n * 32 + nj * 16 + b_r) * (SSTRIDE * 2) + bcolb;
                uint32_t r0, r1, r2, r3;
                ldsm_x4(bd, r0, r1, r2, r3);
                bh[nj * 2][0] = r0; bh[nj * 2][1] = r2;
                bh[nj * 2 + 1][0] = r1; bh[nj * 2 + 1][1] = r3;
                ldsm_x4(bd + TILEB, r0, r1, r2, r3);
                bl[nj * 2][0] = r0; bl[nj * 2][1] = r2;
                bl[nj * 2 + 1][0] = r1; bl[nj * 2 + 1][1] = r3;
            }
            // 3-term split MMA
#pragma unroll
            for (int mi = 0; mi < 4; mi++)
#pragma unroll
                for (int ni = 0; ni < 4; ni++)
                    mma_bf16(acc[mi][ni], ah[mi], bh[ni][0], bh[ni][1]);
#pragma unroll
            for (int mi = 0; mi < 4; mi++)
#pragma unroll
                for (int ni = 0; ni < 4; ni++)
                    mma_bf16(acc[mi][ni], ah[mi], bl[ni][0], bl[ni][1]);
#pragma unroll
            for (int mi = 0; mi < 4; mi++)
#pragma unroll
                for (int ni = 0; ni < 4; ni++)
                    mma_bf16(acc[mi][ni], al[mi], bh[ni][0], bh[ni][1]);
        }
    }

    // Epilogue: acc[mi][ni] fragment: {c0,c1} at (row q, col 2p), {c2,c3} at (row q+8)
    int qrow = lane >> 2;
    int qcol = (lane & 3) * 2;
#pragma unroll
    for (int mi = 0; mi < 4; mi++) {
#pragma unroll
        for (int h = 0; h < 2; h++) {
            int row = brow + warp_m * 64 + mi * 16 + qrow + h * 8;
#pragma unroll
            for (int ni = 0; ni < 4; ni++) {
                int col = bcol + warp_n * 32 + ni * 8 + qcol;
                size_t off = (size_t)row * N + col;
                float o0 = acc[mi][ni][h * 2];
                float o1 = acc[mi][ni][h * 2 + 1];
                if (EPI == 1) {
                    o0 = 1.f / (1.f + expf(-o0));
                    o1 = 1.f / (1.f + expf(-o1));
                } else if (EPI == 3) {
                    const float2 rv = *(const float2*)(res + off);
                    o0 += rv.x; o1 += rv.y;
                } else if (EPI == 4) {
                    const float2 rv = *(const float2*)(res + off);
                    const float2 gv = *(const float2*)(gate + off);
                    o0 = rv.x + gv.x * o0;
                    o1 = rv.y + gv.y * o1;
                }
                if (EPI == 2) {
                    o0 = fmaxf(o0, 0.f); o0 *= o0;
                    o1 = fmaxf(o1, 0.f); o1 *= o1;
                    __nv_bfloat16 h0 = __float2bfloat16(o0);
                    __nv_bfloat16 h1 = __float2bfloat16(o1);
                    __nv_bfloat162 hp; hp.x = h0; hp.y = h1;
                    __nv_bfloat162 lp;
                    lp.x = __float2bfloat16(o0 - __bfloat162float(h0));
                    lp.y = __float2bfloat16(o1 - __bfloat162float(h1));
                    *(__nv_bfloat162*)(Chi + off) = hp;
                    *(__nv_bfloat162*)(Clo + off) = lp;
                } else {
                    float2 ov = make_float2(o0, o1);
                    *(float2*)(Cc + off) = ov;
                }
            }
        }
    }
}

// ---------------------------------------------------------------------------
// Bidirectional WKV; one thread per (b,c). Writes split-bf16 y.
// ---------------------------------------------------------------------------
__global__ __launch_bounds__(256) void wkv_k(const float* __restrict__ r,
                                             const float* __restrict__ k,
                                             const float* __restrict__ v,
                                             const float* __restrict__ w,
                                             const float* __restrict__ u,
                                             __nv_bfloat16* __restrict__ y_hi,
                                             __nv_bfloat16* __restrict__ y_lo,
                                             float* __restrict__ sakv,
                                             float* __restrict__ sak) {
    int gid = blockIdx.x * blockDim.x + threadIdx.x;   // 0 .. B*C-1
    int b = gid >> 10;
    int c = gid & (C - 1);
    float decay = expf(-expf(w[c]));
    float eu = expf(u[c]);
    size_t base = (size_t)b * T * C + c;

    float aA = 0.f, aB = 0.f;
#pragma unroll 4
    for (int t = 0; t < T; t++) {
        size_t o = base + (size_t)t * C;
        float ek = expf(k[o]);
        float kv = ek * v[o];
        sakv[o] = aA;
        sak[o]  = aB;
        aA = aA * decay + kv;
        aB = aB * decay + ek;
    }

    float bA = 0.f, bB = 0.f;
#pragma unroll 4
    for (int t = T - 1; t >= 0; t--) {
        size_t o = base + (size_t)t * C;
        float vv = v[o];
        float ek = expf(k[o]);
        float kv = ek * vv;
        float num = sakv[o] + bA + eu * vv;
        float den = sak[o]  + bB + eu;
        float yv = r[o] * num / (den + 1e-8f);
        __nv_bfloat16 h = __float2bfloat16(yv);
        y_hi[o] = h;
        y_lo[o] = __float2bfloat16(yv - __bfloat162float(h));
        bA = bA * decay + kv;
        bB = bB * decay + ek;
    }
}

// ---------------------------------------------------------------------------
// Host launch
// ---------------------------------------------------------------------------
extern "C" void kernel_launch(void* const* d_in, const int* in_sizes, int n_in,
                              void* d_out, int out_size) {
    const int*   idx     = (const int*)  d_in[0];
    const float* emb     = (const float*)d_in[1];
    const float* ln1_w   = (const float*)d_in[2];
    const float* ln1_b   = (const float*)d_in[3];
    const float* Wr      = (const float*)d_in[4];
    const float* Wk      = (const float*)d_in[5];
    const float* Wv      = (const float*)d_in[6];
    const float* w_decay = (const float*)d_in[7];
    const float* u_bonus = (const float*)d_in[8];
    const float* Wo      = (const float*)d_in[9];
    const float* ln2_w   = (const float*)d_in[10];
    const float* ln2_b   = (const float*)d_in[11];
    const float* Wfk     = (const float*)d_in[12];
    const float* Wfv     = (const float*)d_in[13];
    const float* Wfr     = (const float*)d_in[14];
    const float* lnout_w = (const float*)d_in[15];
    const float* lnout_b = (const float*)d_in[16];
    const float* head_W  = (const float*)d_in[17];
    float* out = (float*)d_out;

    float *x, *r, *k, *v, *sa, *sb;
    __nv_bfloat16 *wth, *wtl, *xnh, *xnl, *yh, *yl, *kfh, *kfl;
    cudaGetSymbolAddress((void**)&x,   g_x);
    cudaGetSymbolAddress((void**)&r,   g_r);
    cudaGetSymbolAddress((void**)&k,   g_k);
    cudaGetSymbolAddress((void**)&v,   g_v);
    cudaGetSymbolAddress((void**)&sa,  g_sakv);
    cudaGetSymbolAddress((void**)&sb,  g_sak);
    cudaGetSymbolAddress((void**)&wth, g_wt_hi);
    cudaGetSymbolAddress((void**)&wtl, g_wt_lo);
    cudaGetSymbolAddress((void**)&xnh, g_xn_hi);
    cudaGetSymbolAddress((void**)&xnl, g_xn_lo);
    cudaGetSymbolAddress((void**)&yh,  g_y_hi);
    cudaGetSymbolAddress((void**)&yl,  g_y_lo);
    cudaGetSymbolAddress((void**)&kfh, g_kf_hi);
    cudaGetSymbolAddress((void**)&kfl, g_kf_lo);

    cudaFuncSetAttribute(gemm_mma<0>, cudaFuncAttributeMaxDynamicSharedMemorySize, GEMM_SMEM);
    cudaFuncSetAttribute(gemm_mma<1>, cudaFuncAttributeMaxDynamicSharedMemorySize, GEMM_SMEM);
    cudaFuncSetAttribute(gemm_mma<2>, cudaFuncAttributeMaxDynamicSharedMemorySize, GEMM_SMEM);
    cudaFuncSetAttribute(gemm_mma<3>, cudaFuncAttributeMaxDynamicSharedMemorySize, GEMM_SMEM);
    cudaFuncSetAttribute(gemm_mma<4>, cudaFuncAttributeMaxDynamicSharedMemorySize, GEMM_SMEM);

    // ---- Weight conversion (transpose + bf16 split) ----
    dim3 cvtBlk(32, 8);
    for (int l = 0; l < L; l++) {
        size_t wb = (size_t)l * WOFF_LAYER;
        const float* wr  = Wr  + (size_t)l * C * C;
        const float* wk  = Wk  + (size_t)l * C * C;
        const float* wv  = Wv  + (size_t)l * C * C;
        const float* wo  = Wo  + (size_t)l * C * C;
        const float* wfr = Wfr + (size_t)l * C * C;
        const float* wfk = Wfk + (size_t)l * C * F;
        const float* wfv = Wfv + (size_t)l * F * C;
        dim3 gCC(C / 32, C / 32);
        convert_transpose_k<<<gCC, cvtBlk>>>(wr,  wth + wb + WOFF_WR,  wtl + wb + WOFF_WR,  C, C);
        convert_transpose_k<<<gCC, cvtBlk>>>(wk,  wth + wb + WOFF_WK,  wtl + wb + WOFF_WK,  C, C);
        convert_transpose_k<<<gCC, cvtBlk>>>(wv,  wth + wb + WOFF_WV,  wtl + wb + WOFF_WV,  C, C);
        convert_transpose_k<<<gCC, cvtBlk>>>(wo,  wth + wb + WOFF_WO,  wtl + wb + WOFF_WO,  C, C);
        convert_transpose_k<<<gCC, cvtBlk>>>(wfr, wth + wb + WOFF_WFR, wtl + wb + WOFF_WFR, C, C);
        convert_transpose_k<<<dim3(F / 32, C / 32), cvtBlk>>>(wfk, wth + wb + WOFF_WFK, wtl + wb + WOFF_WFK, C, F);
        convert_transpose_k<<<dim3(C / 32, F / 32), cvtBlk>>>(wfv, wth + wb + WOFF_WFV, wtl + wb + WOFF_WFV, F, C);
    }
    convert_transpose_k<<<dim3(V / 32, C / 32), cvtBlk>>>(head_W, wth + WOFF_HEAD, wtl + WOFF_HEAD, C, V);

    // ---- Forward ----
    embed_k<<<M, 256>>>(idx, emb, x);

    dim3 gCCg(M / 128, C / 128);   // N = C
    dim3 gCFg(M / 128, F / 128);   // N = F
    dim3 gCVg(M / 128, V / 128);   // N = V (50304/128 = 393)

    for (int l = 0; l < L; l++) {
        size_t wb = (size_t)l * WOFF_LAYER;
        const float* l1w = ln1_w + (size_t)l * C;
        const float* l1b = ln1_b + (size_t)l * C;
        const float* wd  = w_decay + (size_t)l * C;
        const float* ub  = u_bonus + (size_t)l * C;
        const float* l2w = ln2_w + (size_t)l * C;
        const float* l2b = ln2_b + (size_t)l * C;

        // time-mix
        layernorm_k<<<M, 256>>>(x, l1w, l1b, xnh, xnl);
        gemm_mma<1><<<gCCg, 256, GEMM_SMEM>>>(xnh, xnl, wth + wb + WOFF_WR, wtl + wb + WOFF_WR,
                                              r, nullptr, nullptr, nullptr, nullptr, C, C);
        gemm_mma<0><<<gCCg, 256, GEMM_SMEM>>>(xnh, xnl, wth + wb + WOFF_WK, wtl + wb + WOFF_WK,
                                              k, nullptr, nullptr, nullptr, nullptr, C, C);
        gemm_mma<0><<<gCCg, 256, GEMM_SMEM>>>(xnh, xnl, wth + wb + WOFF_WV, wtl + wb + WOFF_WV,
                                              v, nullptr, nullptr, nullptr, nullptr, C, C);
        wkv_k<<<(B * C) / 256, 256>>>(r, k, v, wd, ub, yh, yl, sa, sb);
        gemm_mma<3><<<gCCg, 256, GEMM_SMEM>>>(yh, yl, wth + wb + WOFF_WO, wtl + wb + WOFF_WO,
                                              x, nullptr, nullptr, x, nullptr, C, C);

        // channel-mix
        layernorm_k<<<M, 256>>>(x, l2w, l2b, xnh, xnl);
        gemm_mma<1><<<gCCg, 256, GEMM_SMEM>>>(xnh, xnl, wth + wb + WOFF_WFR, wtl + wb + WOFF_WFR,
                                              r, nullptr, nullptr, nullptr, nullptr, C, C);
        gemm_mma<2><<<gCFg, 256, GEMM_SMEM>>>(xnh, xnl, wth + wb + WOFF_WFK, wtl + wb + WOFF_WFK,
                                              nullptr, kfh, kfl, nullptr, nullptr, F, C);
        gemm_mma<4><<<gCCg, 256, GEMM_SMEM>>>(kfh, kfl, wth + wb + WOFF_WFV, wtl + wb + WOFF_WFV,
                                              x, nullptr, nullptr, x, r, C, F);
    }

    layernorm_k<<<M, 256>>>(x, lnout_w, lnout_b, xnh, xnl);
    gemm_mma<0><<<gCVg, 256, GEMM_SMEM>>>(xnh, xnl, wth + WOFF_HEAD, wtl + WOFF_HEAD,
                                          out, nullptr, nullptr, nullptr, nullptr, V, C);
}

// round 4
// speedup vs baseline: 1.9230x; 1.0888x over previous
#include <cuda_runtime.h>
#include <cuda_bf16.h>
#include <cstdint>
#include <math.h>

// ---------------------------------------------------------------------------
// Problem constants
// ---------------------------------------------------------------------------
constexpr int L = 4;
constexpr int C = 1024;
constexpr int F = 4096;
constexpr int V = 50304;
constexpr int B = 2;
constexpr int T = 1024;
constexpr int M = B * T;            // 2048 rows

// ---------------------------------------------------------------------------
// Converted-weight layout: SAME [K,N] layout as the inputs (no transpose),
// grouped per source array so conversion is pure streaming.
// ---------------------------------------------------------------------------
constexpr size_t MB1 = size_t(C) * C;         // 1,048,576
constexpr size_t O_WR   = 0;                  // [L][C][C]
constexpr size_t O_WK   = 4 * MB1;
constexpr size_t O_WV   = 8 * MB1;
constexpr size_t O_WO   = 12 * MB1;
constexpr size_t O_WFR  = 16 * MB1;
constexpr size_t O_WFK  = 20 * MB1;           // [L][C][F]
constexpr size_t O_WFV  = 36 * MB1;           // [L][F][C]
constexpr size_t O_HEAD = 52 * MB1;           // [C][V]
constexpr size_t WTOTAL = O_HEAD + size_t(V) * C;

__device__ alignas(16) __nv_bfloat16 g_wt_hi[WTOTAL];
__device__ alignas(16) __nv_bfloat16 g_wt_lo[WTOTAL];

__device__ alignas(16) float g_x   [size_t(M) * C];
__device__ alignas(16) float g_r   [size_t(M) * C];
__device__ alignas(16) float g_k   [size_t(M) * C];
__device__ alignas(16) float g_v   [size_t(M) * C];
__device__ alignas(16) float g_sakv[size_t(M) * C];
__device__ alignas(16) float g_sak [size_t(M) * C];
__device__ alignas(16) __nv_bfloat16 g_xn_hi[size_t(M) * C];
__device__ alignas(16) __nv_bfloat16 g_xn_lo[size_t(M) * C];
__device__ alignas(16) __nv_bfloat16 g_y_hi [size_t(M) * C];
__device__ alignas(16) __nv_bfloat16 g_y_lo [size_t(M) * C];
__device__ alignas(16) __nv_bfloat16 g_kf_hi[size_t(M) * F];
__device__ alignas(16) __nv_bfloat16 g_kf_lo[size_t(M) * F];

// ---------------------------------------------------------------------------
// Streaming split conversion: fp32 -> (hi, lo) bf16, same layout. float4 in,
// 8B out per array. No transpose.
// ---------------------------------------------------------------------------
__global__ __launch_bounds__(256) void convert_split_k(
    const float4* __restrict__ src,
    uint2* __restrict__ oh, uint2* __restrict__ ol, size_t n4) {
    size_t stride = (size_t)gridDim.x * blockDim.x;
    for (size_t i = (size_t)blockIdx.x * blockDim.x + threadIdx.x; i < n4; i += stride) {
        float4 w = src[i];
        union { __nv_bfloat162 h[2]; uint2 u; } H, Lo;
        H.h[0].x = __float2bfloat16(w.x);
        H.h[0].y = __float2bfloat16(w.y);
        H.h[1].x = __float2bfloat16(w.z);
        H.h[1].y = __float2bfloat16(w.w);
        Lo.h[0].x = __float2bfloat16(w.x - __bfloat162float(H.h[0].x));
        Lo.h[0].y = __float2bfloat16(w.y - __bfloat162float(H.h[0].y));
        Lo.h[1].x = __float2bfloat16(w.z - __bfloat162float(H.h[1].x));
        Lo.h[1].y = __float2bfloat16(w.w - __bfloat162float(H.h[1].y));
        oh[i] = H.u;
        ol[i] = Lo.u;
    }
}

// ---------------------------------------------------------------------------
// Embedding gather
// ---------------------------------------------------------------------------
__global__ void embed_k(const int* __restrict__ idx,
                        const float* __restrict__ emb,
                        float* __restrict__ x) {
    int row = blockIdx.x;
    int id = idx[row];
    const float4* src = (const float4*)(emb + (size_t)id * C);
    float4* dst = (float4*)(x + (size_t)row * C);
    for (int i = threadIdx.x; i < C / 4; i += blockDim.x) dst[i] = src[i];
}

// ---------------------------------------------------------------------------
// LayerNorm -> split bf16 output
// ---------------------------------------------------------------------------
__global__ __launch_bounds__(256) void layernorm_k(const float* __restrict__ x,
                                                   const float* __restrict__ w,
                                                   const float* __restrict__ b,
                                                   __nv_bfloat16* __restrict__ out_hi,
                                                   __nv_bfloat16* __restrict__ out_lo) {
    __shared__ float red[256];
    int row = blockIdx.x;
    const float* xr = x + (size_t)row * C;
    float v[4];
    float s = 0.f;
#pragma unroll
    for (int i = 0; i < 4; i++) { v[i] = xr[threadIdx.x + 256 * i]; s += v[i]; }
    red[threadIdx.x] = s;
    __syncthreads();
    for (int o = 128; o > 0; o >>= 1) {
        if (threadIdx.x < o) red[threadIdx.x] += red[threadIdx.x + o];
        __syncthreads();
    }
    float mu = red[0] * (1.f / C);
    __syncthreads();
    float s2 = 0.f;
#pragma unroll
    for (int i = 0; i < 4; i++) { float d = v[i] - mu; s2 += d * d; }
    red[threadIdx.x] = s2;
    __syncthreads();
    for (int o = 128; o > 0; o >>= 1) {
        if (threadIdx.x < o) red[threadIdx.x] += red[threadIdx.x + o];
        __syncthreads();
    }
    float rstd = rsqrtf(red[0] * (1.f / C) + 1e-5f);
#pragma unroll
    for (int i = 0; i < 4; i++) {
        int c = threadIdx.x + 256 * i;
        float o = (v[i] - mu) * rstd * w[c] + b[c];
        __nv_bfloat16 h = __float2bfloat16(o);
        size_t off = (size_t)row * C + c;
        out_hi[off] = h;
        out_lo[off] = __float2bfloat16(o - __bfloat162float(h));
    }
}

// ---------------------------------------------------------------------------
// Split-bf16 tensor-core GEMM via mma.sync.
//   out = epi( A[M,K] @ W[K,N] ),  3 MMA terms: Ah*Bh + Ah*Bl + Al*Bh.
//   A: hi/lo bf16 [M,K] row-major.   W: hi/lo bf16 [K,N] row-major (native!).
//   B fragments loaded with ldmatrix.x4.trans (no weight transpose needed).
//   EPI 0 plain fp32 | 1 sigmoid fp32 | 2 relu^2 -> bf16 hi/lo
//   EPI 3 res + acc  | 4 res + gate * acc
// CTA 128x128, BK=32, 8 warps (2x4), warp tile 64x32 (4x4 of m16n8k16).
// 5-stage cp.async pipeline; one commit per iteration (empty commits at tail).
// ---------------------------------------------------------------------------
constexpr int BK = 32;
constexpr int SSTRA = 40;                     // A padded elems/row (80B)
constexpr int SSTRB = 136;                    // B padded elems/row (272B)
constexpr int TA = 128 * SSTRA * 2;           // 10240 B
constexpr int TB = BK * SSTRB * 2;            // 8704 B
constexpr int OFF_AH = 0;
constexpr int OFF_AL = TA;
constexpr int OFF_BH = 2 * TA;
constexpr int OFF_BL = 2 * TA + TB;
constexpr int STAGEB = 2 * TA + 2 * TB;       // 37888 B
constexpr int NSTAGE = 5;
constexpr int GEMM_SMEM = NSTAGE * STAGEB;    // 189440 B

__device__ __forceinline__ uint32_t smem_u32(const void* p) {
    uint32_t a;
    asm("{ .reg .u64 t; cvta.to.shared.u64 t, %1; cvt.u32.u64 %0, t; }"
        : "=r"(a) : "l"(p));
    return a;
}

__device__ __forceinline__ void ldsm_x4(uint32_t addr, uint32_t& r0, uint32_t& r1,
                                        uint32_t& r2, uint32_t& r3) {
    asm volatile("ldmatrix.sync.aligned.m8n8.x4.shared.b16 {%0,%1,%2,%3}, [%4];"
                 : "=r"(r0), "=r"(r1), "=r"(r2), "=r"(r3) : "r"(addr));
}

__device__ __forceinline__ void ldsm_x4_t(uint32_t addr, uint32_t& r0, uint32_t& r1,
                                          uint32_t& r2, uint32_t& r3) {
    asm volatile("ldmatrix.sync.aligned.m8n8.x4.trans.shared.b16 {%0,%1,%2,%3}, [%4];"
                 : "=r"(r0), "=r"(r1), "=r"(r2), "=r"(r3) : "r"(addr));
}

__device__ __forceinline__ void mma_bf16(float* d, const uint32_t* a,
                                         uint32_t b0, uint32_t b1) {
    asm volatile(
        "mma.sync.aligned.m16n8k16.row.col.f32.bf16.bf16.f32 "
        "{%0,%1,%2,%3}, {%4,%5,%6,%7}, {%8,%9}, {%0,%1,%2,%3};"
        : "+f"(d[0]), "+f"(d[1]), "+f"(d[2]), "+f"(d[3])
        : "r"(a[0]), "r"(a[1]), "r"(a[2]), "r"(a[3]), "r"(b0), "r"(b1));
}

__device__ __forceinline__ void cp16(uint32_t sp, const void* gp) {
    asm volatile("cp.async.cg.shared.global [%0], [%1], 16;" :: "r"(sp), "l"(gp));
}

// A tile: 128 rows x 32 k. 64 threads, 2 rows x 4 chunks each.
__device__ __forceinline__ void issue_A(uint32_t dst, const __nv_bfloat16* __restrict__ g,
                                        int brow, int K, int k0, int t64) {
#pragma unroll
    for (int j = 0; j < 2; j++) {
        int r = t64 * 2 + j;
        const __nv_bfloat16* gp = g + (size_t)(brow + r) * K + k0;
        uint32_t sp = dst + r * (SSTRA * 2);
#pragma unroll
        for (int cc = 0; cc < 4; cc++)
            cp16(sp + cc * 16, gp + cc * 8);
    }
}

// B tile: 32 k-rows x 128 n. 64 threads: row = t>>1, 8 chunks of 16B each.
__device__ __forceinline__ void issue_B(uint32_t dst, const __nv_bfloat16* __restrict__ g,
                                        int bcol, int N, int k0, int t64) {
    int r = t64 >> 1;
    int c0 = (t64 & 1) * 8;
    const __nv_bfloat16* gp = g + (size_t)(k0 + r) * N + bcol + c0 * 8;
    uint32_t sp = dst + r * (SSTRB * 2) + c0 * 16;
#pragma unroll
    for (int cc = 0; cc < 8; cc++)
        cp16(sp + cc * 16, gp + cc * 8);
}

template <int EPI>
__global__ __launch_bounds__(256, 1) void gemm_mma(
    const __nv_bfloat16* __restrict__ Ah, const __nv_bfloat16* __restrict__ Al,
    const __nv_bfloat16* __restrict__ Bh, const __nv_bfloat16* __restrict__ Bl,
    float* __restrict__ Cc,
    __nv_bfloat16* __restrict__ Chi, __nv_bfloat16* __restrict__ Clo,
    const float* __restrict__ res, const float* __restrict__ gate,
    int N, int K) {
    extern __shared__ __align__(128) char sm[];
    uint32_t smem = smem_u32(sm);
    int tid = threadIdx.x;
    int wid = tid >> 5;
    int lane = tid & 31;
    int brow = blockIdx.x * 128;
    int bcol = blockIdx.y * 128;
    int warp_m = wid & 1;          // 0..1 (64 rows each)
    int warp_n = wid >> 1;         // 0..3 (32 cols each)

    int tile_id = tid >> 6;        // 0:Ah 1:Al 2:Bh 3:Bl
    int t64 = tid & 63;

    float acc[4][4][4];
#pragma unroll
    for (int i = 0; i < 4; i++)
#pragma unroll
        for (int j = 0; j < 4; j++)
#pragma unroll
            for (int q = 0; q < 4; q++) acc[i][j][q] = 0.f;

    int nch = K >> 5;              // BK = 32

    // prologue: stages 0..3
#pragma unroll
    for (int s = 0; s < 4; s++) {
        uint32_t sb = smem + s * STAGEB;
        if (tile_id == 0)      issue_A(sb + OFF_AH, Ah, brow, K, s * BK, t64);
        else if (tile_id == 1) issue_A(sb + OFF_AL, Al, brow, K, s * BK, t64);
        else if (tile_id == 2) issue_B(sb + OFF_BH, Bh, bcol, N, s * BK, t64);
        else                   issue_B(sb + OFF_BL, Bl, bcol, N, s * BK, t64);
        asm volatile("cp.async.commit_group;");
    }

    // ldmatrix lane address components
    int a_r = (lane & 15);                    // A: row within 16-row block
    int a_k = ((lane >> 4) << 3);             // A: 0 or 8 k-offset
    int b_kr = (lane & 15);                   // B: k-row within 16
    int b_nf = ((lane >> 4) << 3);            // B: 0 or 8 n-offset

#pragma unroll 1
    for (int c = 0; c < nch; c++) {
        asm volatile("cp.async.wait_group 3;");
        __syncthreads();
        if (c + 4 < nch) {
            uint32_t sb = smem + ((c + 4) % NSTAGE) * STAGEB;
            int k0 = (c + 4) * BK;
            if (tile_id == 0)      issue_A(sb + OFF_AH, Ah, brow, K, k0, t64);
            else if (tile_id == 1) issue_A(sb + OFF_AL, Al, brow, K, k0, t64);
            else if (tile_id == 2) issue_B(sb + OFF_BH, Bh, bcol, N, k0, t64);
            else                   issue_B(sb + OFF_BL, Bl, bcol, N, k0, t64);
        }
        asm volatile("cp.async.commit_group;");   // empty commit keeps count exact

        uint32_t sbase = smem + (c % NSTAGE) * STAGEB;
#pragma unroll
        for (int ks = 0; ks < 2; ks++) {
            int kk = ks * 16;
            uint32_t ah[4][4], al[4][4], bh[4][2], bl[4][2];
            // A fragments (hi & lo)
            uint32_t acol = (uint32_t)(kk + a_k) * 2;
#pragma unroll
            for (int mi = 0; mi < 4; mi++) {
                uint32_t ad = sbase + OFF_AH +
                              (warp_m * 64 + mi * 16 + a_r) * (SSTRA * 2) + acol;
                ldsm_x4(ad, ah[mi][0], ah[mi][1], ah[mi][2], ah[mi][3]);
                ldsm_x4(ad + TA, al[mi][0], al[mi][1], al[mi][2], al[mi][3]);
            }
            // B fragments via trans-ldmatrix from [K,N] tile
#pragma unroll
            for (int nj = 0; nj < 2; nj++) {
                uint32_t bd = sbase + OFF_BH + (kk + b_kr) * (SSTRB * 2) +
                              (warp_n * 32 + nj * 16 + b_nf) * 2;
                uint32_t r0, r1, r2, r3;
                ldsm_x4_t(bd, r0, r1, r2, r3);
                bh[nj * 2][0] = r0;     bh[nj * 2][1] = r1;
                bh[nj * 2 + 1][0] = r2; bh[nj * 2 + 1][1] = r3;
                ldsm_x4_t(bd + TB, r0, r1, r2, r3);
                bl[nj * 2][0] = r0;     bl[nj * 2][1] = r1;
                bl[nj * 2 + 1][0] = r2; bl[nj * 2 + 1][1] = r3;
            }
            // 3-term split MMA
#pragma unroll
            for (int mi = 0; mi < 4; mi++)
#pragma unroll
                for (int ni = 0; ni < 4; ni++)
                    mma_bf16(acc[mi][ni], ah[mi], bh[ni][0], bh[ni][1]);
#pragma unroll
            for (int mi = 0; mi < 4; mi++)
#pragma unroll
                for (int ni = 0; ni < 4; ni++)
                    mma_bf16(acc[mi][ni], ah[mi], bl[ni][0], bl[ni][1]);
#pragma unroll
            for (int mi = 0; mi < 4; mi++)
#pragma unroll
                for (int ni = 0; ni < 4; ni++)
                    mma_bf16(acc[mi][ni], al[mi], bh[ni][0], bh[ni][1]);
        }
    }

    // Epilogue
    int qrow = lane >> 2;
    int qcol = (lane & 3) * 2;
#pragma unroll
    for (int mi = 0; mi < 4; mi++) {
#pragma unroll
        for (int h = 0; h < 2; h++) {
            int row = brow + warp_m * 64 + mi * 16 + qrow + h * 8;
#pragma unroll
            for (int ni = 0; ni < 4; ni++) {
                int col = bcol + warp_n * 32 + ni * 8 + qcol;
                size_t off = (size_t)row * N + col;
                float o0 = acc[mi][ni][h * 2];
                float o1 = acc[mi][ni][h * 2 + 1];
                if (EPI == 1) {
                    o0 = 1.f / (1.f + expf(-o0));
                    o1 = 1.f / (1.f + expf(-o1));
                } else if (EPI == 3) {
                    const float2 rv = *(const float2*)(res + off);
                    o0 += rv.x; o1 += rv.y;
                } else if (EPI == 4) {
                    const float2 rv = *(const float2*)(res + off);
                    const float2 gv = *(const float2*)(gate + off);
                    o0 = rv.x + gv.x * o0;
                    o1 = rv.y + gv.y * o1;
                }
                if (EPI == 2) {
                    o0 = fmaxf(o0, 0.f); o0 *= o0;
                    o1 = fmaxf(o1, 0.f); o1 *= o1;
                    __nv_bfloat16 h0 = __float2bfloat16(o0);
                    __nv_bfloat16 h1 = __float2bfloat16(o1);
                    __nv_bfloat162 hp; hp.x = h0; hp.y = h1;
                    __nv_bfloat162 lp;
                    lp.x = __float2bfloat16(o0 - __bfloat162float(h0));
                    lp.y = __float2bfloat16(o1 - __bfloat162float(h1));
                    *(__nv_bfloat162*)(Chi + off) = hp;
                    *(__nv_bfloat162*)(Clo + off) = lp;
                } else {
                    float2 ov = make_float2(o0, o1);
                    *(float2*)(Cc + off) = ov;
                }
            }
        }
    }
}

// ---------------------------------------------------------------------------
// Bidirectional WKV; one thread per (b,c). Writes split-bf16 y.
// ---------------------------------------------------------------------------
__global__ __launch_bounds__(256) void wkv_k(const float* __restrict__ r,
                                             const float* __restrict__ k,
                                             const float* __restrict__ v,
                                             const float* __restrict__ w,
                                             const float* __restrict__ u,
                                             __nv_bfloat16* __restrict__ y_hi,
                                             __nv_bfloat16* __restrict__ y_lo,
                                             float* __restrict__ sakv,
                                             float* __restrict__ sak) {
    int gid = blockIdx.x * blockDim.x + threadIdx.x;   // 0 .. B*C-1
    int b = gid >> 10;
    int c = gid & (C - 1);
    float decay = expf(-expf(w[c]));
    float eu = expf(u[c]);
    size_t base = (size_t)b * T * C + c;

    float aA = 0.f, aB = 0.f;
#pragma unroll 4
    for (int t = 0; t < T; t++) {
        size_t o = base + (size_t)t * C;
        float ek = expf(k[o]);
        float kv = ek * v[o];
        sakv[o] = aA;
        sak[o]  = aB;
        aA = aA * decay + kv;
        aB = aB * decay + ek;
    }

    float bA = 0.f, bB = 0.f;
#pragma unroll 4
    for (int t = T - 1; t >= 0; t--) {
        size_t o = base + (size_t)t * C;
        float vv = v[o];
        float ek = expf(k[o]);
        float kv = ek * vv;
        float num = sakv[o] + bA + eu * vv;
        float den = sak[o]  + bB + eu;
        float yv = r[o] * num / (den + 1e-8f);
        __nv_bfloat16 h = __float2bfloat16(yv);
        y_hi[o] = h;
        y_lo[o] = __float2bfloat16(yv - __bfloat162float(h));
        bA = bA * decay + kv;
        bB = bB * decay + ek;
    }
}

// ---------------------------------------------------------------------------
// Host launch
// ---------------------------------------------------------------------------
extern "C" void kernel_launch(void* const* d_in, const int* in_sizes, int n_in,
                              void* d_out, int out_size) {
    const int*   idx     = (const int*)  d_in[0];
    const float* emb     = (const float*)d_in[1];
    const float* ln1_w   = (const float*)d_in[2];
    const float* ln1_b   = (const float*)d_in[3];
    const float* Wr      = (const float*)d_in[4];
    const float* Wk      = (const float*)d_in[5];
    const float* Wv      = (const float*)d_in[6];
    const float* w_decay = (const float*)d_in[7];
    const float* u_bonus = (const float*)d_in[8];
    const float* Wo      = (const float*)d_in[9];
    const float* ln2_w   = (const float*)d_in[10];
    const float* ln2_b   = (const float*)d_in[11];
    const float* Wfk     = (const float*)d_in[12];
    const float* Wfv     = (const float*)d_in[13];
    const float* Wfr     = (const float*)d_in[14];
    const float* lnout_w = (const float*)d_in[15];
    const float* lnout_b = (const float*)d_in[16];
    const float* head_W  = (const float*)d_in[17];
    float* out = (float*)d_out;

    float *x, *r, *k, *v, *sa, *sb;
    __nv_bfloat16 *wth, *wtl, *xnh, *xnl, *yh, *yl, *kfh, *kfl;
    cudaGetSymbolAddress((void**)&x,   g_x);
    cudaGetSymbolAddress((void**)&r,   g_r);
    cudaGetSymbolAddress((void**)&k,   g_k);
    cudaGetSymbolAddress((void**)&v,   g_v);
    cudaGetSymbolAddress((void**)&sa,  g_sakv);
    cudaGetSymbolAddress((void**)&sb,  g_sak);
    cudaGetSymbolAddress((void**)&wth, g_wt_hi);
    cudaGetSymbolAddress((void**)&wtl, g_wt_lo);
    cudaGetSymbolAddress((void**)&xnh, g_xn_hi);
    cudaGetSymbolAddress((void**)&xnl, g_xn_lo);
    cudaGetSymbolAddress((void**)&yh,  g_y_hi);
    cudaGetSymbolAddress((void**)&yl,  g_y_lo);
    cudaGetSymbolAddress((void**)&kfh, g_kf_hi);
    cudaGetSymbolAddress((void**)&kfl, g_kf_lo);

    cudaFuncSetAttribute(gemm_mma<0>, cudaFuncAttributeMaxDynamicSharedMemorySize, GEMM_SMEM);
    cudaFuncSetAttribute(gemm_mma<1>, cudaFuncAttributeMaxDynamicSharedMemorySize, GEMM_SMEM);
    cudaFuncSetAttribute(gemm_mma<2>, cudaFuncAttributeMaxDynamicSharedMemorySize, GEMM_SMEM);
    cudaFuncSetAttribute(gemm_mma<3>, cudaFuncAttributeMaxDynamicSharedMemorySize, GEMM_SMEM);
    cudaFuncSetAttribute(gemm_mma<4>, cudaFuncAttributeMaxDynamicSharedMemorySize, GEMM_SMEM);

    // ---- Streaming weight conversion (no transpose): 8 launches ----
    auto cvt = [&](const float* src, size_t dstOff, size_t nElems) {
        size_t n4 = nElems / 4;
        int blocks = (int)((n4 + 255) / 256);
        if (blocks > 2048) blocks = 2048;
        convert_split_k<<<blocks, 256>>>((const float4*)src,
                                         (uint2*)(wth + dstOff),
                                         (uint2*)(wtl + dstOff), n4);
    };
    cvt(Wr,     O_WR,   size_t(L) * C * C);
    cvt(Wk,     O_WK,   size_t(L) * C * C);
    cvt(Wv,     O_WV,   size_t(L) * C * C);
    cvt(Wo,     O_WO,   size_t(L) * C * C);
    cvt(Wfr,    O_WFR,  size_t(L) * C * C);
    cvt(Wfk,    O_WFK,  size_t(L) * C * F);
    cvt(Wfv,    O_WFV,  size_t(L) * F * C);
    cvt(head_W, O_HEAD, size_t(V) * C);

    // ---- Forward ----
    embed_k<<<M, 256>>>(idx, emb, x);

    dim3 gCCg(M / 128, C / 128);   // N = C
    dim3 gCFg(M / 128, F / 128);   // N = F
    dim3 gCVg(M / 128, V / 128);   // N = V (393)

    for (int l = 0; l < L; l++) {
        size_t wcc = (size_t)l * C * C;
        size_t wcf = (size_t)l * C * F;
        const float* l1w = ln1_w + (size_t)l * C;
        const float* l1b = ln1_b + (size_t)l * C;
        const float* wd  = w_decay + (size_t)l * C;
        const float* ub  = u_bonus + (size_t)l * C;
        const float* l2w = ln2_w + (size_t)l * C;
        const float* l2b = ln2_b + (size_t)l * C;

        // time-mix
        layernorm_k<<<M, 256>>>(x, l1w, l1b, xnh, xnl);
        gemm_mma<1><<<gCCg, 256, GEMM_SMEM>>>(xnh, xnl, wth + O_WR + wcc, wtl + O_WR + wcc,
                                              r, nullptr, nullptr, nullptr, nullptr, C, C);
        gemm_mma<0><<<gCCg, 256, GEMM_SMEM>>>(xnh, xnl, wth + O_WK + wcc, wtl + O_WK + wcc,
                                              k, nullptr, nullptr, nullptr, nullptr, C, C);
        gemm_mma<0><<<gCCg, 256, GEMM_SMEM>>>(xnh, xnl, wth + O_WV + wcc, wtl + O_WV + wcc,
                                              v, nullptr, nullptr, nullptr, nullptr, C, C);
        wkv_k<<<(B * C) / 256, 256>>>(r, k, v, wd, ub, yh, yl, sa, sb);
        gemm_mma<3><<<gCCg, 256, GEMM_SMEM>>>(yh, yl, wth + O_WO + wcc, wtl + O_WO + wcc,
                                              x, nullptr, nullptr, x, nullptr, C, C);

        // channel-mix
        layernorm_k<<<M, 256>>>(x, l2w, l2b, xnh, xnl);
        gemm_mma<1><<<gCCg, 256, GEMM_SMEM>>>(xnh, xnl, wth + O_WFR + wcc, wtl + O_WFR + wcc,
                                              r, nullptr, nullptr, nullptr, nullptr, C, C);
        gemm_mma<2><<<gCFg, 256, GEMM_SMEM>>>(xnh, xnl, wth + O_WFK + wcf, wtl + O_WFK + wcf,
                                              nullptr, kfh, kfl, nullptr, nullptr, F, C);
        gemm_mma<4><<<gCCg, 256, GEMM_SMEM>>>(kfh, kfl, wth + O_WFV + wcf, wtl + O_WFV + wcf,
                                              x, nullptr, nullptr, x, r, C, F);
    }

    layernorm_k<<<M, 256>>>(x, lnout_w, lnout_b, xnh, xnl);
    gemm_mma<0><<<gCVg, 256, GEMM_SMEM>>>(xnh, xnl, wth + O_HEAD, wtl + O_HEAD,
                                          out, nullptr, nullptr, nullptr, nullptr, V, C);
}

// round 5
// speedup vs baseline: 2.4203x; 1.2586x over previous
#include <cuda_runtime.h>
#include <cuda_bf16.h>
#include <cstdint>
#include <math.h>

// ---------------------------------------------------------------------------
// Problem constants
// ---------------------------------------------------------------------------
constexpr int L = 4;
constexpr int C = 1024;
constexpr int F = 4096;
constexpr int V = 50304;
constexpr int B = 2;
constexpr int T = 1024;
constexpr int M = B * T;            // 2048 rows
constexpr int CH = 16;              // wkv chunks
constexpr int CL = 64;              // wkv chunk length (CH*CL == T)

// ---------------------------------------------------------------------------
// Converted-weight layout: SAME [K,N] layout as inputs (no transpose).
// ---------------------------------------------------------------------------
constexpr size_t MB1 = size_t(C) * C;         // 1,048,576
constexpr size_t O_WR   = 0;                  // [L][C][C]
constexpr size_t O_WK   = 4 * MB1;
constexpr size_t O_WV   = 8 * MB1;
constexpr size_t O_WO   = 12 * MB1;
constexpr size_t O_WFR  = 16 * MB1;
constexpr size_t O_WFK  = 20 * MB1;           // [L][C][F]
constexpr size_t O_WFV  = 36 * MB1;           // [L][F][C]
constexpr size_t O_HEAD = 52 * MB1;           // [C][V]
constexpr size_t WTOTAL = O_HEAD + size_t(V) * C;

__device__ alignas(16) __nv_bfloat16 g_wt_hi[WTOTAL];
__device__ alignas(16) __nv_bfloat16 g_wt_lo[WTOTAL];

__device__ alignas(16) float g_x   [size_t(M) * C];
__device__ alignas(16) float g_r   [size_t(M) * C];
__device__ alignas(16) float g_k   [size_t(M) * C];
__device__ alignas(16) float g_v   [size_t(M) * C];
__device__ alignas(16) float g_sakv[size_t(M) * C];
__device__ alignas(16) float g_sak [size_t(M) * C];
__device__ alignas(16) __nv_bfloat16 g_xn_hi[size_t(M) * C];
__device__ alignas(16) __nv_bfloat16 g_xn_lo[size_t(M) * C];
__device__ alignas(16) __nv_bfloat16 g_y_hi [size_t(M) * C];
__device__ alignas(16) __nv_bfloat16 g_y_lo [size_t(M) * C];
__device__ alignas(16) __nv_bfloat16 g_kf_hi[size_t(M) * F];
__device__ alignas(16) __nv_bfloat16 g_kf_lo[size_t(M) * F];

// wkv chunk-scan scratch: [B][CH][C]
constexpr int AGG = B * CH * C;    // 32768
__device__ alignas(16) float g_aggFkv[AGG];
__device__ alignas(16) float g_aggFk [AGG];
__device__ alignas(16) float g_aggBkv[AGG];
__device__ alignas(16) float g_aggBk [AGG];
__device__ alignas(16) float g_iniFkv[AGG];
__device__ alignas(16) float g_iniFk [AGG];
__device__ alignas(16) float g_iniBkv[AGG];
__device__ alignas(16) float g_iniBk [AGG];

// ---------------------------------------------------------------------------
// Merged streaming split conversion: all 8 weight arrays in ONE launch.
// Segment boundaries in float4 units.
// ---------------------------------------------------------------------------
constexpr size_t N4_CC = size_t(L) * C * C / 4;    // 1,048,576
constexpr size_t N4_CF = size_t(L) * C * F / 4;    // 4,194,304
constexpr size_t N4_HD = size_t(V) * C / 4;        // 12,877,824
constexpr size_t CV_B0 = N4_CC;                    // Wr
constexpr size_t CV_B1 = CV_B0 + N4_CC;            // Wk
constexpr size_t CV_B2 = CV_B1 + N4_CC;            // Wv
constexpr size_t CV_B3 = CV_B2 + N4_CC;            // Wo
constexpr size_t CV_B4 = CV_B3 + N4_CC;            // Wfr
constexpr size_t CV_B5 = CV_B4 + N4_CF;            // Wfk
constexpr size_t CV_B6 = CV_B5 + N4_CF;            // Wfv
constexpr size_t CV_TOT = CV_B6 + N4_HD;           // + head

__global__ __launch_bounds__(256) void convert_all_k(
    const float4* __restrict__ wr, const float4* __restrict__ wk,
    const float4* __restrict__ wv, const float4* __restrict__ wo,
    const float4* __restrict__ wfr, const float4* __restrict__ wfk,
    const float4* __restrict__ wfv, const float4* __restrict__ hd,
    uint2* __restrict__ oh, uint2* __restrict__ ol) {
    size_t stride = (size_t)gridDim.x * blockDim.x;
    for (size_t i = (size_t)blockIdx.x * blockDim.x + threadIdx.x; i < CV_TOT;
         i += stride) {
        const float4* src;
        size_t dst;
        if (i < CV_B0)      { src = wr;  dst = O_WR  / 4 + i; src += i; }
        else if (i < CV_B1) { src = wk  + (i - CV_B0); dst = O_WK  / 4 + (i - CV_B0); }
        else if (i < CV_B2) { src = wv  + (i - CV_B1); dst = O_WV  / 4 + (i - CV_B1); }
        else if (i < CV_B3) { src = wo  + (i - CV_B2); dst = O_WO  / 4 + (i - CV_B2); }
        else if (i < CV_B4) { src = wfr + (i - CV_B3); dst = O_WFR / 4 + (i - CV_B3); }
        else if (i < CV_B5) { src = wfk + (i - CV_B4); dst = O_WFK / 4 + (i - CV_B4); }
        else if (i < CV_B6) { src = wfv + (i - CV_B5); dst = O_WFV / 4 + (i - CV_B5); }
        else                { src = hd  + (i - CV_B6); dst = O_HEAD/ 4 + (i - CV_B6); }
        float4 w = *src;
        union { __nv_bfloat162 h[2]; uint2 u; } H, Lo;
        H.h[0].x = __float2bfloat16(w.x);
        H.h[0].y = __float2bfloat16(w.y);
        H.h[1].x = __float2bfloat16(w.z);
        H.h[1].y = __float2bfloat16(w.w);
        Lo.h[0].x = __float2bfloat16(w.x - __bfloat162float(H.h[0].x));
        Lo.h[0].y = __float2bfloat16(w.y - __bfloat162float(H.h[0].y));
        Lo.h[1].x = __float2bfloat16(w.z - __bfloat162float(H.h[1].x));
        Lo.h[1].y = __float2bfloat16(w.w - __bfloat162float(H.h[1].y));
        oh[dst] = H.u;
        ol[dst] = Lo.u;
    }
}

// ---------------------------------------------------------------------------
// Embedding gather
// ---------------------------------------------------------------------------
__global__ void embed_k(const int* __restrict__ idx,
                        const float* __restrict__ emb,
                        float* __restrict__ x) {
    int row = blockIdx.x;
    int id = idx[row];
    const float4* src = (const float4*)(emb + (size_t)id * C);
    float4* dst = (float4*)(x + (size_t)row * C);
    for (int i = threadIdx.x; i < C / 4; i += blockDim.x) dst[i] = src[i];
}

// ---------------------------------------------------------------------------
// LayerNorm -> split bf16 output
// ---------------------------------------------------------------------------
__global__ __launch_bounds__(256) void layernorm_k(const float* __restrict__ x,
                                                   const float* __restrict__ w,
                                                   const float* __restrict__ b,
                                                   __nv_bfloat16* __restrict__ out_hi,
                                                   __nv_bfloat16* __restrict__ out_lo) {
    __shared__ float red[256];
    int row = blockIdx.x;
    const float* xr = x + (size_t)row * C;
    float v[4];
    float s = 0.f;
#pragma unroll
    for (int i = 0; i < 4; i++) { v[i] = xr[threadIdx.x + 256 * i]; s += v[i]; }
    red[threadIdx.x] = s;
    __syncthreads();
    for (int o = 128; o > 0; o >>= 1) {
        if (threadIdx.x < o) red[threadIdx.x] += red[threadIdx.x + o];
        __syncthreads();
    }
    float mu = red[0] * (1.f / C);
    __syncthreads();
    float s2 = 0.f;
#pragma unroll
    for (int i = 0; i < 4; i++) { float d = v[i] - mu; s2 += d * d; }
    red[threadIdx.x] = s2;
    __syncthreads();
    for (int o = 128; o > 0; o >>= 1) {
        if (threadIdx.x < o) red[threadIdx.x] += red[threadIdx.x + o];
        __syncthreads();
    }
    float rstd = rsqrtf(red[0] * (1.f / C) + 1e-5f);
#pragma unroll
    for (int i = 0; i < 4; i++) {
        int c = threadIdx.x + 256 * i;
        float o = (v[i] - mu) * rstd * w[c] + b[c];
        __nv_bfloat16 h = __float2bfloat16(o);
        size_t off = (size_t)row * C + c;
        out_hi[off] = h;
        out_lo[off] = __float2bfloat16(o - __bfloat162float(h));
    }
}

// ---------------------------------------------------------------------------
// Split-bf16 tensor-core GEMM via mma.sync (unchanged from round 4).
// ---------------------------------------------------------------------------
constexpr int BK = 32;
constexpr int SSTRA = 40;
constexpr int SSTRB = 136;
constexpr int TA = 128 * SSTRA * 2;
constexpr int TB = BK * SSTRB * 2;
constexpr int OFF_AH = 0;
constexpr int OFF_AL = TA;
constexpr int OFF_BH = 2 * TA;
constexpr int OFF_BL = 2 * TA + TB;
constexpr int STAGEB = 2 * TA + 2 * TB;
constexpr int NSTAGE = 5;
constexpr int GEMM_SMEM = NSTAGE * STAGEB;    // 189440 B

__device__ __forceinline__ uint32_t smem_u32(const void* p) {
    uint32_t a;
    asm("{ .reg .u64 t; cvta.to.shared.u64 t, %1; cvt.u32.u64 %0, t; }"
        : "=r"(a) : "l"(p));
    return a;
}

__device__ __forceinline__ void ldsm_x4(uint32_t addr, uint32_t& r0, uint32_t& r1,
                                        uint32_t& r2, uint32_t& r3) {
    asm volatile("ldmatrix.sync.aligned.m8n8.x4.shared.b16 {%0,%1,%2,%3}, [%4];"
                 : "=r"(r0), "=r"(r1), "=r"(r2), "=r"(r3) : "r"(addr));
}

__device__ __forceinline__ void ldsm_x4_t(uint32_t addr, uint32_t& r0, uint32_t& r1,
                                          uint32_t& r2, uint32_t& r3) {
    asm volatile("ldmatrix.sync.aligned.m8n8.x4.trans.shared.b16 {%0,%1,%2,%3}, [%4];"
                 : "=r"(r0), "=r"(r1), "=r"(r2), "=r"(r3) : "r"(addr));
}

__device__ __forceinline__ void mma_bf16(float* d, const uint32_t* a,
                                         uint32_t b0, uint32_t b1) {
    asm volatile(
        "mma.sync.aligned.m16n8k16.row.col.f32.bf16.bf16.f32 "
        "{%0,%1,%2,%3}, {%4,%5,%6,%7}, {%8,%9}, {%0,%1,%2,%3};"
        : "+f"(d[0]), "+f"(d[1]), "+f"(d[2]), "+f"(d[3])
        : "r"(a[0]), "r"(a[1]), "r"(a[2]), "r"(a[3]), "r"(b0), "r"(b1));
}

__device__ __forceinline__ void cp16(uint32_t sp, const void* gp) {
    asm volatile("cp.async.cg.shared.global [%0], [%1], 16;" :: "r"(sp), "l"(gp));
}

__device__ __forceinline__ void issue_A(uint32_t dst, const __nv_bfloat16* __restrict__ g,
                                        int brow, int K, int k0, int t64) {
#pragma unroll
    for (int j = 0; j < 2; j++) {
        int r = t64 * 2 + j;
        const __nv_bfloat16* gp = g + (size_t)(brow + r) * K + k0;
        uint32_t sp = dst + r * (SSTRA * 2);
#pragma unroll
        for (int cc = 0; cc < 4; cc++)
            cp16(sp + cc * 16, gp + cc * 8);
    }
}

__device__ __forceinline__ void issue_B(uint32_t dst, const __nv_bfloat16* __restrict__ g,
                                        int bcol, int N, int k0, int t64) {
    int r = t64 >> 1;
    int c0 = (t64 & 1) * 8;
    const __nv_bfloat16* gp = g + (size_t)(k0 + r) * N + bcol + c0 * 8;
    uint32_t sp = dst + r * (SSTRB * 2) + c0 * 16;
#pragma unroll
    for (int cc = 0; cc < 8; cc++)
        cp16(sp + cc * 16, gp + cc * 8);
}

template <int EPI>
__global__ __launch_bounds__(256, 1) void gemm_mma(
    const __nv_bfloat16* __restrict__ Ah, const __nv_bfloat16* __restrict__ Al,
    const __nv_bfloat16* __restrict__ Bh, const __nv_bfloat16* __restrict__ Bl,
    float* __restrict__ Cc,
    __nv_bfloat16* __restrict__ Chi, __nv_bfloat16* __restrict__ Clo,
    const float* __restrict__ res, const float* __restrict__ gate,
    int N, int K) {
    extern __shared__ __align__(128) char sm[];
    uint32_t smem = smem_u32(sm);
    int tid = threadIdx.x;
    int wid = tid >> 5;
    int lane = tid & 31;
    int brow = blockIdx.x * 128;
    int bcol = blockIdx.y * 128;
    int warp_m = wid & 1;
    int warp_n = wid >> 1;

    int tile_id = tid >> 6;
    int t64 = tid & 63;

    float acc[4][4][4];
#pragma unroll
    for (int i = 0; i < 4; i++)
#pragma unroll
        for (int j = 0; j < 4; j++)
#pragma unroll
            for (int q = 0; q < 4; q++) acc[i][j][q] = 0.f;

    int nch = K >> 5;

#pragma unroll
    for (int s = 0; s < 4; s++) {
        uint32_t sb = smem + s * STAGEB;
        if (tile_id == 0)      issue_A(sb + OFF_AH, Ah, brow, K, s * BK, t64);
        else if (tile_id == 1) issue_A(sb + OFF_AL, Al, brow, K, s * BK, t64);
        else if (tile_id == 2) issue_B(sb + OFF_BH, Bh, bcol, N, s * BK, t64);
        else                   issue_B(sb + OFF_BL, Bl, bcol, N, s * BK, t64);
        asm volatile("cp.async.commit_group;");
    }

    int a_r = (lane & 15);
    int a_k = ((lane >> 4) << 3);
    int b_kr = (lane & 15);
    int b_nf = ((lane >> 4) << 3);

#pragma unroll 1
    for (int c = 0; c < nch; c++) {
        asm volatile("cp.async.wait_group 3;");
        __syncthreads();
        if (c + 4 < nch) {
            uint32_t sb = smem + ((c + 4) % NSTAGE) * STAGEB;
            int k0 = (c + 4) * BK;
            if (tile_id == 0)      issue_A(sb + OFF_AH, Ah, brow, K, k0, t64);
            else if (tile_id == 1) issue_A(sb + OFF_AL, Al, brow, K, k0, t64);
            else if (tile_id == 2) issue_B(sb + OFF_BH, Bh, bcol, N, k0, t64);
            else                   issue_B(sb + OFF_BL, Bl, bcol, N, k0, t64);
        }
        asm volatile("cp.async.commit_group;");

        uint32_t sbase = smem + (c % NSTAGE) * STAGEB;
#pragma unroll
        for (int ks = 0; ks < 2; ks++) {
            int kk = ks * 16;
            uint32_t ah[4][4], al[4][4], bh[4][2], bl[4][2];
            uint32_t acol = (uint32_t)(kk + a_k) * 2;
#pragma unroll
            for (int mi = 0; mi < 4; mi++) {
                uint32_t ad = sbase + OFF_AH +
                              (warp_m * 64 + mi * 16 + a_r) * (SSTRA * 2) + acol;
                ldsm_x4(ad, ah[mi][0], ah[mi][1], ah[mi][2], ah[mi][3]);
                ldsm_x4(ad + TA, al[mi][0], al[mi][1], al[mi][2], al[mi][3]);
            }
#pragma unroll
            for (int nj = 0; nj < 2; nj++) {
                uint32_t bd = sbase + OFF_BH + (kk + b_kr) * (SSTRB * 2) +
                              (warp_n * 32 + nj * 16 + b_nf) * 2;
                uint32_t r0, r1, r2, r3;
                ldsm_x4_t(bd, r0, r1, r2, r3);
                bh[nj * 2][0] = r0;     bh[nj * 2][1] = r1;
                bh[nj * 2 + 1][0] = r2; bh[nj * 2 + 1][1] = r3;
                ldsm_x4_t(bd + TB, r0, r1, r2, r3);
                bl[nj * 2][0] = r0;     bl[nj * 2][1] = r1;
                bl[nj * 2 + 1][0] = r2; bl[nj * 2 + 1][1] = r3;
            }
#pragma unroll
            for (int mi = 0; mi < 4; mi++)
#pragma unroll
                for (int ni = 0; ni < 4; ni++)
                    mma_bf16(acc[mi][ni], ah[mi], bh[ni][0], bh[ni][1]);
#pragma unroll
            for (int mi = 0; mi < 4; mi++)
#pragma unroll
                for (int ni = 0; ni < 4; ni++)
                    mma_bf16(acc[mi][ni], ah[mi], bl[ni][0], bl[ni][1]);
#pragma unroll
            for (int mi = 0; mi < 4; mi++)
#pragma unroll
                for (int ni = 0; ni < 4; ni++)
                    mma_bf16(acc[mi][ni], al[mi], bh[ni][0], bh[ni][1]);
        }
    }

    int qrow = lane >> 2;
    int qcol = (lane & 3) * 2;
#pragma unroll
    for (int mi = 0; mi < 4; mi++) {
#pragma unroll
        for (int h = 0; h < 2; h++) {
            int row = brow + warp_m * 64 + mi * 16 + qrow + h * 8;
#pragma unroll
            for (int ni = 0; ni < 4; ni++) {
                int col = bcol + warp_n * 32 + ni * 8 + qcol;
                size_t off = (size_t)row * N + col;
                float o0 = acc[mi][ni][h * 2];
                float o1 = acc[mi][ni][h * 2 + 1];
                if (EPI == 1) {
                    o0 = 1.f / (1.f + expf(-o0));
                    o1 = 1.f / (1.f + expf(-o1));
                } else if (EPI == 3) {
                    const float2 rv = *(const float2*)(res + off);
                    o0 += rv.x; o1 += rv.y;
                } else if (EPI == 4) {
                    const float2 rv = *(const float2*)(res + off);
                    const float2 gv = *(const float2*)(gate + off);
                    o0 = rv.x + gv.x * o0;
                    o1 = rv.y + gv.y * o1;
                }
                if (EPI == 2) {
                    o0 = fmaxf(o0, 0.f); o0 *= o0;
                    o1 = fmaxf(o1, 0.f); o1 *= o1;
                    __nv_bfloat16 h0 = __float2bfloat16(o0);
                    __nv_bfloat16 h1 = __float2bfloat16(o1);
                    __nv_bfloat162 hp; hp.x = h0; hp.y = h1;
                    __nv_bfloat162 lp;
                    lp.x = __float2bfloat16(o0 - __bfloat162float(h0));
                    lp.y = __float2bfloat16(o1 - __bfloat162float(h1));
                    *(__nv_bfloat162*)(Chi + off) = hp;
                    *(__nv_bfloat162*)(Clo + off) = lp;
                } else {
                    float2 ov = make_float2(o0, o1);
                    *(float2*)(Cc + off) = ov;
                }
            }
        }
    }
}

// ---------------------------------------------------------------------------
// Chunk-parallel bidirectional WKV.
//   s <- s*d + x is associative: over a CL-chunk, s_out = s_in*d^CL + S.
//   W1: per (b,c,chunk) compute fwd aggregate S (and bwd aggregate R) in one
//       pass.  W2: per (b,c) 16-step scan of aggregates -> per-chunk inits.
//   W3: per (b,c,chunk) replay: fwd exclusive -> sakv/sak; bwd exclusive
//       combines with them into y (split bf16).
// ---------------------------------------------------------------------------
__global__ __launch_bounds__(256) void wkv_agg_k(
    const float* __restrict__ k, const float* __restrict__ v,
    const float* __restrict__ w,
    float* __restrict__ aFkv, float* __restrict__ aFk,
    float* __restrict__ aBkv, float* __restrict__ aBk) {
    int gid = blockIdx.x * blockDim.x + threadIdx.x;   // 0 .. B*CH*C-1
    int c = gid & (C - 1);
    int ch = (gid >> 10) & (CH - 1);
    int b = gid >> 14;
    float d = expf(-expf(w[c]));
    size_t base = (size_t)b * T * C + (size_t)ch * CL * C + c;

    float fkv = 0.f, fk = 0.f, bkv = 0.f, bk = 0.f, pw = 1.f;
#pragma unroll 4
    for (int i = 0; i < CL; i++) {
        size_t o = base + (size_t)i * C;
        float ek = expf(k[o]);
        float kv = ek * v[o];
        fkv = fkv * d + kv;
        fk  = fk  * d + ek;
        bkv += kv * pw;
        bk  += ek * pw;
        pw *= d;
    }
    aFkv[gid] = fkv; aFk[gid] = fk;
    aBkv[gid] = bkv; aBk[gid] = bk;
}

__global__ __launch_bounds__(256) void wkv_scan_k(
    const float* __restrict__ w,
    const float* __restrict__ aFkv, const float* __restrict__ aFk,
    const float* __restrict__ aBkv, const float* __restrict__ aBk,
    float* __restrict__ iFkv, float* __restrict__ iFk,
    float* __restrict__ iBkv, float* __restrict__ iBk) {
    int gid = blockIdx.x * blockDim.x + threadIdx.x;   // 0 .. B*C-1
    int c = gid & (C - 1);
    int b = gid >> 10;
    float D = expf(-(float)CL * expf(w[c]));           // d^CL
    int base = b * CH * C + c;

    float skv = 0.f, sk = 0.f;
#pragma unroll
    for (int ch = 0; ch < CH; ch++) {
        int ai = base + ch * C;
        iFkv[ai] = skv; iFk[ai] = sk;
        skv = skv * D + aFkv[ai];
        sk  = sk  * D + aFk[ai];
    }
    skv = 0.f; sk = 0.f;
#pragma unroll
    for (int ch = CH - 1; ch >= 0; ch--) {
        int ai = base + ch * C;
        iBkv[ai] = skv; iBk[ai] = sk;
        skv = skv * D + aBkv[ai];
        sk  = sk  * D + aBk[ai];
    }
}

__global__ __launch_bounds__(256) void wkv_apply_k(
    const float* __restrict__ r, const float* __restrict__ k,
    const float* __restrict__ v, const float* __restrict__ w,
    const float* __restrict__ u,
    const float* __restrict__ iFkv, const float* __restrict__ iFk,
    const float* __restrict__ iBkv, const float* __restrict__ iBk,
    __nv_bfloat16* __restrict__ y_hi, __nv_bfloat16* __restrict__ y_lo,
    float* __restrict__ sakv, float* __restrict__ sak) {
    int gid = blockIdx.x * blockDim.x + threadIdx.x;   // 0 .. B*CH*C-1
    int c = gid & (C - 1);
    int ch = (gid >> 10) & (CH - 1);
    int b = gid >> 14;
    float d = expf(-expf(w[c]));
    float eu = expf(u[c]);
    size_t base = (size_t)b * T * C + (size_t)ch * CL * C + c;

    // forward exclusive replay
    float fkv = iFkv[gid], fk = iFk[gid];
#pragma unroll 4
    for (int i = 0; i < CL; i++) {
        size_t o = base + (size_t)i * C;
        float ek = expf(k[o]);
        float kv = ek * v[o];
        sakv[o] = fkv;
        sak[o]  = fk;
        fkv = fkv * d + kv;
        fk  = fk  * d + ek;
    }
    // backward exclusive + combine
    float bkv = iBkv[gid], bk = iBk[gid];
#pragma unroll 4
    for (int i = CL - 1; i >= 0; i--) {
        size_t o = base + (size_t)i * C;
        float vv = v[o];
        float ek = expf(k[o]);
        float kv = ek * vv;
        float num = sakv[o] + bkv + eu * vv;
        float den = sak[o]  + bk  + eu;
        float yv = r[o] * num / (den + 1e-8f);
        __nv_bfloat16 h = __float2bfloat16(yv);
        y_hi[o] = h;
        y_lo[o] = __float2bfloat16(yv - __bfloat162float(h));
        bkv = bkv * d + kv;
        bk  = bk  * d + ek;
    }
}

// ---------------------------------------------------------------------------
// Host launch
// ---------------------------------------------------------------------------
extern "C" void kernel_launch(void* const* d_in, const int* in_sizes, int n_in,
                              void* d_out, int out_size) {
    const int*   idx     = (const int*)  d_in[0];
    const float* emb     = (const float*)d_in[1];
    const float* ln1_w   = (const float*)d_in[2];
    const float* ln1_b   = (const float*)d_in[3];
    const float* Wr      = (const float*)d_in[4];
    const float* Wk      = (const float*)d_in[5];
    const float* Wv      = (const float*)d_in[6];
    const float* w_decay = (const float*)d_in[7];
    const float* u_bonus = (const float*)d_in[8];
    const float* Wo      = (const float*)d_in[9];
    const float* ln2_w   = (const float*)d_in[10];
    const float* ln2_b   = (const float*)d_in[11];
    const float* Wfk     = (const float*)d_in[12];
    const float* Wfv     = (const float*)d_in[13];
    const float* Wfr     = (const float*)d_in[14];
    const float* lnout_w = (const float*)d_in[15];
    const float* lnout_b = (const float*)d_in[16];
    const float* head_W  = (const float*)d_in[17];
    float* out = (float*)d_out;

    float *x, *r, *k, *v, *sa, *sb;
    float *aFkv, *aFk, *aBkv, *aBk, *iFkv, *iFk, *iBkv, *iBk;
    __nv_bfloat16 *wth, *wtl, *xnh, *xnl, *yh, *yl, *kfh, *kfl;
    cudaGetSymbolAddress((void**)&x,    g_x);
    cudaGetSymbolAddress((void**)&r,    g_r);
    cudaGetSymbolAddress((void**)&k,    g_k);
    cudaGetSymbolAddress((void**)&v,    g_v);
    cudaGetSymbolAddress((void**)&sa,   g_sakv);
    cudaGetSymbolAddress((void**)&sb,   g_sak);
    cudaGetSymbolAddress((void**)&wth,  g_wt_hi);
    cudaGetSymbolAddress((void**)&wtl,  g_wt_lo);
    cudaGetSymbolAddress((void**)&xnh,  g_xn_hi);
    cudaGetSymbolAddress((void**)&xnl,  g_xn_lo);
    cudaGetSymbolAddress((void**)&yh,   g_y_hi);
    cudaGetSymbolAddress((void**)&yl,   g_y_lo);
    cudaGetSymbolAddress((void**)&kfh,  g_kf_hi);
    cudaGetSymbolAddress((void**)&kfl,  g_kf_lo);
    cudaGetSymbolAddress((void**)&aFkv, g_aggFkv);
    cudaGetSymbolAddress((void**)&aFk,  g_aggFk);
    cudaGetSymbolAddress((void**)&aBkv, g_aggBkv);
    cudaGetSymbolAddress((void**)&aBk,  g_aggBk);
    cudaGetSymbolAddress((void**)&iFkv, g_iniFkv);
    cudaGetSymbolAddress((void**)&iFk,  g_iniFk);
    cudaGetSymbolAddress((void**)&iBkv, g_iniBkv);
    cudaGetSymbolAddress((void**)&iBk,  g_iniBk);

    cudaFuncSetAttribute(gemm_mma<0>, cudaFuncAttributeMaxDynamicSharedMemorySize, GEMM_SMEM);
    cudaFuncSetAttribute(gemm_mma<1>, cudaFuncAttributeMaxDynamicSharedMemorySize, GEMM_SMEM);
    cudaFuncSetAttribute(gemm_mma<2>, cudaFuncAttributeMaxDynamicSharedMemorySize, GEMM_SMEM);
    cudaFuncSetAttribute(gemm_mma<3>, cudaFuncAttributeMaxDynamicSharedMemorySize, GEMM_SMEM);
    cudaFuncSetAttribute(gemm_mma<4>, cudaFuncAttributeMaxDynamicSharedMemorySize, GEMM_SMEM);

    // ---- ONE merged weight-conversion launch ----
    convert_all_k<<<2048, 256>>>((const float4*)Wr, (const float4*)Wk,
                                 (const float4*)Wv, (const float4*)Wo,
                                 (const float4*)Wfr, (const float4*)Wfk,
                                 (const float4*)Wfv, (const float4*)head_W,
                                 (uint2*)wth, (uint2*)wtl);

    // ---- Forward ----
    embed_k<<<M, 256>>>(idx, emb, x);

    dim3 gCCg(M / 128, C / 128);
    dim3 gCFg(M / 128, F / 128);
    dim3 gCVg(M / 128, V / 128);

    for (int l = 0; l < L; l++) {
        size_t wcc = (size_t)l * C * C;
        size_t wcf = (size_t)l * C * F;
        const float* l1w = ln1_w + (size_t)l * C;
        const float* l1b = ln1_b + (size_t)l * C;
        const float* wd  = w_decay + (size_t)l * C;
        const float* ub  = u_bonus + (size_t)l * C;
        const float* l2w = ln2_w + (size_t)l * C;
        const float* l2b = ln2_b + (size_t)l * C;

        // time-mix
        layernorm_k<<<M, 256>>>(x, l1w, l1b, xnh, xnl);
        gemm_mma<1><<<gCCg, 256, GEMM_SMEM>>>(xnh, xnl, wth + O_WR + wcc, wtl + O_WR + wcc,
                                              r, nullptr, nullptr, nullptr, nullptr, C, C);
        gemm_mma<0><<<gCCg, 256, GEMM_SMEM>>>(xnh, xnl, wth + O_WK + wcc, wtl + O_WK + wcc,
                                              k, nullptr, nullptr, nullptr, nullptr, C, C);
        gemm_mma<0><<<gCCg, 256, GEMM_SMEM>>>(xnh, xnl, wth + O_WV + wcc, wtl + O_WV + wcc,
                                              v, nullptr, nullptr, nullptr, nullptr, C, C);
        // chunk-parallel wkv
        wkv_agg_k<<<(B * CH * C) / 256, 256>>>(k, v, wd, aFkv, aFk, aBkv, aBk);
        wkv_scan_k<<<(B * C) / 256, 256>>>(wd, aFkv, aFk, aBkv, aBk,
                                           iFkv, iFk, iBkv, iBk);
        wkv_apply_k<<<(B * CH * C) / 256, 256>>>(r, k, v, wd, ub,
                                                 iFkv, iFk, iBkv, iBk,
                                                 yh, yl, sa, sb);
        gemm_mma<3><<<gCCg, 256, GEMM_SMEM>>>(yh, yl, wth + O_WO + wcc, wtl + O_WO + wcc,
                                              x, nullptr, nullptr, x, nullptr, C, C);

        // channel-mix
        layernorm_k<<<M, 256>>>(x, l2w, l2b, xnh, xnl);
        gemm_mma<1><<<gCCg, 256, GEMM_SMEM>>>(xnh, xnl, wth + O_WFR + wcc, wtl + O_WFR + wcc,
                                              r, nullptr, nullptr, nullptr, nullptr, C, C);
        gemm_mma<2><<<gCFg, 256, GEMM_SMEM>>>(xnh, xnl, wth + O_WFK + wcf, wtl + O_WFK + wcf,
                                              nullptr, kfh, kfl, nullptr, nullptr, F, C);
        gemm_mma<4><<<gCCg, 256, GEMM_SMEM>>>(kfh, kfl, wth + O_WFV + wcf, wtl + O_WFV + wcf,
                                              x, nullptr, nullptr, x, r, C, F);
    }

    layernorm_k<<<M, 256>>>(x, lnout_w, lnout_b, xnh, xnl);
    gemm_mma<0><<<gCVg, 256, GEMM_SMEM>>>(xnh, xnl, wth + O_HEAD, wtl + O_HEAD,
                                          out, nullptr, nullptr, nullptr, nullptr, V, C);
}

// round 6
// speedup vs baseline: 2.7024x; 1.1166x over previous
#include <cuda_runtime.h>
#include <cuda_bf16.h>
#include <cstdint>
#include <math.h>

// ---------------------------------------------------------------------------
// Problem constants
// ---------------------------------------------------------------------------
constexpr int L = 4;
constexpr int C = 1024;
constexpr int F = 4096;
constexpr int V = 50304;
constexpr int B = 2;
constexpr int T = 1024;
constexpr int M = B * T;            // 2048 rows
constexpr int CH = 16;              // wkv chunks
constexpr int CL = 64;              // wkv chunk length (CH*CL == T)

// ---------------------------------------------------------------------------
// Converted-weight layout: SAME [K,N] layout as inputs (no transpose).
// ---------------------------------------------------------------------------
constexpr size_t MB1 = size_t(C) * C;         // 1,048,576
constexpr size_t O_WR   = 0;                  // [L][C][C]
constexpr size_t O_WK   = 4 * MB1;
constexpr size_t O_WV   = 8 * MB1;
constexpr size_t O_WO   = 12 * MB1;
constexpr size_t O_WFR  = 16 * MB1;
constexpr size_t O_WFK  = 20 * MB1;           // [L][C][F]
constexpr size_t O_WFV  = 36 * MB1;           // [L][F][C]
constexpr size_t O_HEAD = 52 * MB1;           // [C][V]
constexpr size_t WTOTAL = O_HEAD + size_t(V) * C;

__device__ alignas(16) __nv_bfloat16 g_wt_hi[WTOTAL];
__device__ alignas(16) __nv_bfloat16 g_wt_lo[WTOTAL];

__device__ alignas(16) float g_x   [size_t(M) * C];
__device__ alignas(16) float g_r   [size_t(M) * C];
__device__ alignas(16) float g_k   [size_t(M) * C];
__device__ alignas(16) float g_v   [size_t(M) * C];
__device__ alignas(16) float g_sakv[size_t(M) * C];
__device__ alignas(16) float g_sak [size_t(M) * C];
__device__ alignas(16) __nv_bfloat16 g_xn_hi[size_t(M) * C];
__device__ alignas(16) __nv_bfloat16 g_xn_lo[size_t(M) * C];
__device__ alignas(16) __nv_bfloat16 g_y_hi [size_t(M) * C];
__device__ alignas(16) __nv_bfloat16 g_y_lo [size_t(M) * C];
__device__ alignas(16) __nv_bfloat16 g_kf_hi[size_t(M) * F];
__device__ alignas(16) __nv_bfloat16 g_kf_lo[size_t(M) * F];

// wkv chunk-scan scratch: [B][CH][C]
constexpr int AGG = B * CH * C;    // 32768
__device__ alignas(16) float g_aggFkv[AGG];
__device__ alignas(16) float g_aggFk [AGG];
__device__ alignas(16) float g_aggBkv[AGG];
__device__ alignas(16) float g_aggBk [AGG];
__device__ alignas(16) float g_iniFkv[AGG];
__device__ alignas(16) float g_iniFk [AGG];
__device__ alignas(16) float g_iniBkv[AGG];
__device__ alignas(16) float g_iniBk [AGG];

// ---------------------------------------------------------------------------
// Merged streaming split conversion (one launch).
// ---------------------------------------------------------------------------
constexpr size_t N4_CC = size_t(L) * C * C / 4;
constexpr size_t N4_CF = size_t(L) * C * F / 4;
constexpr size_t N4_HD = size_t(V) * C / 4;
constexpr size_t CV_B0 = N4_CC;
constexpr size_t CV_B1 = CV_B0 + N4_CC;
constexpr size_t CV_B2 = CV_B1 + N4_CC;
constexpr size_t CV_B3 = CV_B2 + N4_CC;
constexpr size_t CV_B4 = CV_B3 + N4_CC;
constexpr size_t CV_B5 = CV_B4 + N4_CF;
constexpr size_t CV_B6 = CV_B5 + N4_CF;
constexpr size_t CV_TOT = CV_B6 + N4_HD;

__global__ __launch_bounds__(256) void convert_all_k(
    const float4* __restrict__ wr, const float4* __restrict__ wk,
    const float4* __restrict__ wv, const float4* __restrict__ wo,
    const float4* __restrict__ wfr, const float4* __restrict__ wfk,
    const float4* __restrict__ wfv, const float4* __restrict__ hd,
    uint2* __restrict__ oh, uint2* __restrict__ ol) {
    size_t stride = (size_t)gridDim.x * blockDim.x;
    for (size_t i = (size_t)blockIdx.x * blockDim.x + threadIdx.x; i < CV_TOT;
         i += stride) {
        const float4* src;
        size_t dst;
        if (i < CV_B0)      { src = wr + i; dst = O_WR  / 4 + i; }
        else if (i < CV_B1) { src = wk  + (i - CV_B0); dst = O_WK  / 4 + (i - CV_B0); }
        else if (i < CV_B2) { src = wv  + (i - CV_B1); dst = O_WV  / 4 + (i - CV_B1); }
        else if (i < CV_B3) { src = wo  + (i - CV_B2); dst = O_WO  / 4 + (i - CV_B2); }
        else if (i < CV_B4) { src = wfr + (i - CV_B3); dst = O_WFR / 4 + (i - CV_B3); }
        else if (i < CV_B5) { src = wfk + (i - CV_B4); dst = O_WFK / 4 + (i - CV_B4); }
        else if (i < CV_B6) { src = wfv + (i - CV_B5); dst = O_WFV / 4 + (i - CV_B5); }
        else                { src = hd  + (i - CV_B6); dst = O_HEAD/ 4 + (i - CV_B6); }
        float4 w = *src;
        union { __nv_bfloat162 h[2]; uint2 u; } H, Lo;
        H.h[0].x = __float2bfloat16(w.x);
        H.h[0].y = __float2bfloat16(w.y);
        H.h[1].x = __float2bfloat16(w.z);
        H.h[1].y = __float2bfloat16(w.w);
        Lo.h[0].x = __float2bfloat16(w.x - __bfloat162float(H.h[0].x));
        Lo.h[0].y = __float2bfloat16(w.y - __bfloat162float(H.h[0].y));
        Lo.h[1].x = __float2bfloat16(w.z - __bfloat162float(H.h[1].x));
        Lo.h[1].y = __float2bfloat16(w.w - __bfloat162float(H.h[1].y));
        oh[dst] = H.u;
        ol[dst] = Lo.u;
    }
}

// ---------------------------------------------------------------------------
// Embedding gather
// ---------------------------------------------------------------------------
__global__ void embed_k(const int* __restrict__ idx,
                        const float* __restrict__ emb,
                        float* __restrict__ x) {
    int row = blockIdx.x;
    int id = idx[row];
    const float4* src = (const float4*)(emb + (size_t)id * C);
    float4* dst = (float4*)(x + (size_t)row * C);
    for (int i = threadIdx.x; i < C / 4; i += blockDim.x) dst[i] = src[i];
}

// ---------------------------------------------------------------------------
// LayerNorm -> split bf16 output
// ---------------------------------------------------------------------------
__global__ __launch_bounds__(256) void layernorm_k(const float* __restrict__ x,
                                                   const float* __restrict__ w,
                                                   const float* __restrict__ b,
                                                   __nv_bfloat16* __restrict__ out_hi,
                                                   __nv_bfloat16* __restrict__ out_lo) {
    __shared__ float red[256];
    int row = blockIdx.x;
    const float* xr = x + (size_t)row * C;
    float v[4];
    float s = 0.f;
#pragma unroll
    for (int i = 0; i < 4; i++) { v[i] = xr[threadIdx.x + 256 * i]; s += v[i]; }
    red[threadIdx.x] = s;
    __syncthreads();
    for (int o = 128; o > 0; o >>= 1) {
        if (threadIdx.x < o) red[threadIdx.x] += red[threadIdx.x + o];
        __syncthreads();
    }
    float mu = red[0] * (1.f / C);
    __syncthreads();
    float s2 = 0.f;
#pragma unroll
    for (int i = 0; i < 4; i++) { float d = v[i] - mu; s2 += d * d; }
    red[threadIdx.x] = s2;
    __syncthreads();
    for (int o = 128; o > 0; o >>= 1) {
        if (threadIdx.x < o) red[threadIdx.x] += red[threadIdx.x + o];
        __syncthreads();
    }
    float rstd = rsqrtf(red[0] * (1.f / C) + 1e-5f);
#pragma unroll
    for (int i = 0; i < 4; i++) {
        int c = threadIdx.x + 256 * i;
        float o = (v[i] - mu) * rstd * w[c] + b[c];
        __nv_bfloat16 h = __float2bfloat16(o);
        size_t off = (size_t)row * C + c;
        out_hi[off] = h;
        out_lo[off] = __float2bfloat16(o - __bfloat162float(h));
    }
}

// ---------------------------------------------------------------------------
// Split-bf16 tensor-core GEMM via mma.sync — 512 threads / 16 warps.
//   CTA tile 128x128, BK=32, warp grid 4(m) x 4(n), warp tile 32x32.
//   3 MMA terms: Ah*Bh + Ah*Bl + Al*Bh (fp32 acc).
//   EPI 0 plain | 1 sigmoid | 2 relu^2->bf16 split | 3 res+acc | 4 res+gate*acc
// ---------------------------------------------------------------------------
constexpr int BK = 32;
constexpr int SSTRA = 40;                     // A row pad (80B)
constexpr int SSTRB = 136;                    // B row pad (272B)
constexpr int TA = 128 * SSTRA * 2;           // 10240 B
constexpr int TB = BK * SSTRB * 2;            // 8704 B
constexpr int OFF_AH = 0;
constexpr int OFF_AL = TA;
constexpr int OFF_BH = 2 * TA;
constexpr int OFF_BL = 2 * TA + TB;
constexpr int STAGEB = 2 * TA + 2 * TB;       // 37888 B
constexpr int NSTAGE = 5;
constexpr int GEMM_SMEM = NSTAGE * STAGEB;    // 189440 B
constexpr int GTHREADS = 512;

__device__ __forceinline__ uint32_t smem_u32(const void* p) {
    uint32_t a;
    asm("{ .reg .u64 t; cvta.to.shared.u64 t, %1; cvt.u32.u64 %0, t; }"
        : "=r"(a) : "l"(p));
    return a;
}

__device__ __forceinline__ void ldsm_x4(uint32_t addr, uint32_t& r0, uint32_t& r1,
                                        uint32_t& r2, uint32_t& r3) {
    asm volatile("ldmatrix.sync.aligned.m8n8.x4.shared.b16 {%0,%1,%2,%3}, [%4];"
                 : "=r"(r0), "=r"(r1), "=r"(r2), "=r"(r3) : "r"(addr));
}

__device__ __forceinline__ void ldsm_x4_t(uint32_t addr, uint32_t& r0, uint32_t& r1,
                                          uint32_t& r2, uint32_t& r3) {
    asm volatile("ldmatrix.sync.aligned.m8n8.x4.trans.shared.b16 {%0,%1,%2,%3}, [%4];"
                 : "=r"(r0), "=r"(r1), "=r"(r2), "=r"(r3) : "r"(addr));
}

__device__ __forceinline__ void mma_bf16(float* d, const uint32_t* a,
                                         uint32_t b0, uint32_t b1) {
    asm volatile(
        "mma.sync.aligned.m16n8k16.row.col.f32.bf16.bf16.f32 "
        "{%0,%1,%2,%3}, {%4,%5,%6,%7}, {%8,%9}, {%0,%1,%2,%3};"
        : "+f"(d[0]), "+f"(d[1]), "+f"(d[2]), "+f"(d[3])
        : "r"(a[0]), "r"(a[1]), "r"(a[2]), "r"(a[3]), "r"(b0), "r"(b1));
}

__device__ __forceinline__ void cp16(uint32_t sp, const void* gp) {
    asm volatile("cp.async.cg.shared.global [%0], [%1], 16;" :: "r"(sp), "l"(gp));
}

// A tile: 128 rows x 32 k (64B/row). 128 threads: 1 row, 4 cp16 each.
__device__ __forceinline__ void issue_A(uint32_t dst, const __nv_bfloat16* __restrict__ g,
                                        int brow, int K, int k0, int t128) {
    int r = t128;
    const __nv_bfloat16* gp = g + (size_t)(brow + r) * K + k0;
    uint32_t sp = dst + r * (SSTRA * 2);
#pragma unroll
    for (int cc = 0; cc < 4; cc++)
        cp16(sp + cc * 16, gp + cc * 8);
}

// B tile: 32 k-rows x 128 n (256B/row = 16 chunks). 128 threads: 4 chunks each.
__device__ __forceinline__ void issue_B(uint32_t dst, const __nv_bfloat16* __restrict__ g,
                                        int bcol, int N, int k0, int t128) {
    int r = t128 >> 2;
    int c0 = (t128 & 3) * 4;
    const __nv_bfloat16* gp = g + (size_t)(k0 + r) * N + bcol + c0 * 8;
    uint32_t sp = dst + r * (SSTRB * 2) + c0 * 16;
#pragma unroll
    for (int cc = 0; cc < 4; cc++)
        cp16(sp + cc * 16, gp + cc * 8);
}

template <int EPI>
__global__ __launch_bounds__(GTHREADS, 1) void gemm_mma(
    const __nv_bfloat16* __restrict__ Ah, const __nv_bfloat16* __restrict__ Al,
    const __nv_bfloat16* __restrict__ Bh, const __nv_bfloat16* __restrict__ Bl,
    float* __restrict__ Cc,
    __nv_bfloat16* __restrict__ Chi, __nv_bfloat16* __restrict__ Clo,
    const float* __restrict__ res, const float* __restrict__ gate,
    int N, int K) {
    extern __shared__ __align__(128) char sm[];
    uint32_t smem = smem_u32(sm);
    int tid = threadIdx.x;
    int wid = tid >> 5;
    int lane = tid & 31;
    int brow = blockIdx.x * 128;
    int bcol = blockIdx.y * 128;
    int warp_m = wid & 3;          // 0..3 (32 rows each)
    int warp_n = wid >> 2;         // 0..3 (32 cols each)

    int tile_id = tid >> 7;        // 0:Ah 1:Al 2:Bh 3:Bl
    int t128 = tid & 127;

    float acc[2][4][4];
#pragma unroll
    for (int i = 0; i < 2; i++)
#pragma unroll
        for (int j = 0; j < 4; j++)
#pragma unroll
            for (int q = 0; q < 4; q++) acc[i][j][q] = 0.f;

    int nch = K >> 5;              // BK = 32

#pragma unroll
    for (int s = 0; s < 4; s++) {
        uint32_t sb = smem + s * STAGEB;
        if (tile_id == 0)      issue_A(sb + OFF_AH, Ah, brow, K, s * BK, t128);
        else if (tile_id == 1) issue_A(sb + OFF_AL, Al, brow, K, s * BK, t128);
        else if (tile_id == 2) issue_B(sb + OFF_BH, Bh, bcol, N, s * BK, t128);
        else                   issue_B(sb + OFF_BL, Bl, bcol, N, s * BK, t128);
        asm volatile("cp.async.commit_group;");
    }

    int a_r = (lane & 15);                    // A: row within 16-row block
    int a_k = ((lane >> 4) << 3);             // A: 0 or 8 k-offset
    int b_kr = (lane & 15);                   // B: k-row within 16
    int b_nf = ((lane >> 4) << 3);            // B: 0 or 8 n-offset

#pragma unroll 1
    for (int c = 0; c < nch; c++) {
        asm volatile("cp.async.wait_group 3;");
        __syncthreads();
        if (c + 4 < nch) {
            uint32_t sb = smem + ((c + 4) % NSTAGE) * STAGEB;
            int k0 = (c + 4) * BK;
            if (tile_id == 0)      issue_A(sb + OFF_AH, Ah, brow, K, k0, t128);
            else if (tile_id == 1) issue_A(sb + OFF_AL, Al, brow, K, k0, t128);
            else if (tile_id == 2) issue_B(sb + OFF_BH, Bh, bcol, N, k0, t128);
            else                   issue_B(sb + OFF_BL, Bl, bcol, N, k0, t128);
        }
        asm volatile("cp.async.commit_group;");

        uint32_t sbase = smem + (c % NSTAGE) * STAGEB;
#pragma unroll
        for (int ks = 0; ks < 2; ks++) {
            int kk = ks * 16;
            uint32_t ah[2][4], al[2][4], bh[4][2], bl[4][2];
            uint32_t acol = (uint32_t)(kk + a_k) * 2;
#pragma unroll
            for (int mi = 0; mi < 2; mi++) {
                uint32_t ad = sbase + OFF_AH +
                              (warp_m * 32 + mi * 16 + a_r) * (SSTRA * 2) + acol;
                ldsm_x4(ad, ah[mi][0], ah[mi][1], ah[mi][2], ah[mi][3]);
                ldsm_x4(ad + TA, al[mi][0], al[mi][1], al[mi][2], al[mi][3]);
            }
#pragma unroll
            for (int nj = 0; nj < 2; nj++) {
                uint32_t bd = sbase + OFF_BH + (kk + b_kr) * (SSTRB * 2) +
                              (warp_n * 32 + nj * 16 + b_nf) * 2;
                uint32_t r0, r1, r2, r3;
                ldsm_x4_t(bd, r0, r1, r2, r3);
                bh[nj * 2][0] = r0;     bh[nj * 2][1] = r1;
                bh[nj * 2 + 1][0] = r2; bh[nj * 2 + 1][1] = r3;
                ldsm_x4_t(bd + TB, r0, r1, r2, r3);
                bl[nj * 2][0] = r0;     bl[nj * 2][1] = r1;
                bl[nj * 2 + 1][0] = r2; bl[nj * 2 + 1][1] = r3;
            }
#pragma unroll
            for (int mi = 0; mi < 2; mi++)
#pragma unroll
                for (int ni = 0; ni < 4; ni++)
                    mma_bf16(acc[mi][ni], ah[mi], bh[ni][0], bh[ni][1]);
#pragma unroll
            for (int mi = 0; mi < 2; mi++)
#pragma unroll
                for (int ni = 0; ni < 4; ni++)
                    mma_bf16(acc[mi][ni], ah[mi], bl[ni][0], bl[ni][1]);
#pragma unroll
            for (int mi = 0; mi < 2; mi++)
#pragma unroll
                for (int ni = 0; ni < 4; ni++)
                    mma_bf16(acc[mi][ni], al[mi], bh[ni][0], bh[ni][1]);
        }
    }

    int qrow = lane >> 2;
    int qcol = (lane & 3) * 2;
#pragma unroll
    for (int mi = 0; mi < 2; mi++) {
#pragma unroll
        for (int h = 0; h < 2; h++) {
            int row = brow + warp_m * 32 + mi * 16 + qrow + h * 8;
#pragma unroll
            for (int ni = 0; ni < 4; ni++) {
                int col = bcol + warp_n * 32 + ni * 8 + qcol;
                size_t off = (size_t)row * N + col;
                float o0 = acc[mi][ni][h * 2];
                float o1 = acc[mi][ni][h * 2 + 1];
                if (EPI == 1) {
                    o0 = 1.f / (1.f + expf(-o0));
                    o1 = 1.f / (1.f + expf(-o1));
                } else if (EPI == 3) {
                    const float2 rv = *(const float2*)(res + off);
                    o0 += rv.x; o1 += rv.y;
                } else if (EPI == 4) {
                    const float2 rv = *(const float2*)(res + off);
                    const float2 gv = *(const float2*)(gate + off);
                    o0 = rv.x + gv.x * o0;
                    o1 = rv.y + gv.y * o1;
                }
                if (EPI == 2) {
                    o0 = fmaxf(o0, 0.f); o0 *= o0;
                    o1 = fmaxf(o1, 0.f); o1 *= o1;
                    __nv_bfloat16 h0 = __float2bfloat16(o0);
                    __nv_bfloat16 h1 = __float2bfloat16(o1);
                    __nv_bfloat162 hp; hp.x = h0; hp.y = h1;
                    __nv_bfloat162 lp;
                    lp.x = __float2bfloat16(o0 - __bfloat162float(h0));
                    lp.y = __float2bfloat16(o1 - __bfloat162float(h1));
                    *(__nv_bfloat162*)(Chi + off) = hp;
                    *(__nv_bfloat162*)(Clo + off) = lp;
                } else {
                    float2 ov = make_float2(o0, o1);
                    *(float2*)(Cc + off) = ov;
                }
            }
        }
    }
}

// ---------------------------------------------------------------------------
// Chunk-parallel bidirectional WKV (3 kernels, unchanged from round 5).
// ---------------------------------------------------------------------------
__global__ __launch_bounds__(256) void wkv_agg_k(
    const float* __restrict__ k, const float* __restrict__ v,
    const float* __restrict__ w,
    float* __restrict__ aFkv, float* __restrict__ aFk,
    float* __restrict__ aBkv, float* __restrict__ aBk) {
    int gid = blockIdx.x * blockDim.x + threadIdx.x;   // 0 .. B*CH*C-1
    int c = gid & (C - 1);
    int ch = (gid >> 10) & (CH - 1);
    int b = gid >> 14;
    float d = expf(-expf(w[c]));
    size_t base = (size_t)b * T * C + (size_t)ch * CL * C + c;

    float fkv = 0.f, fk = 0.f, bkv = 0.f, bk = 0.f, pw = 1.f;
#pragma unroll 4
    for (int i = 0; i < CL; i++) {
        size_t o = base + (size_t)i * C;
        float ek = expf(k[o]);
        float kv = ek * v[o];
        fkv = fkv * d + kv;
        fk  = fk  * d + ek;
        bkv += kv * pw;
        bk  += ek * pw;
        pw *= d;
    }
    aFkv[gid] = fkv; aFk[gid] = fk;
    aBkv[gid] = bkv; aBk[gid] = bk;
}

__global__ __launch_bounds__(256) void wkv_scan_k(
    const float* __restrict__ w,
    const float* __restrict__ aFkv, const float* __restrict__ aFk,
    const float* __restrict__ aBkv, const float* __restrict__ aBk,
    float* __restrict__ iFkv, float* __restrict__ iFk,
    float* __restrict__ iBkv, float* __restrict__ iBk) {
    int gid = blockIdx.x * blockDim.x + threadIdx.x;   // 0 .. B*C-1
    int c = gid & (C - 1);
    int b = gid >> 10;
    float D = expf(-(float)CL * expf(w[c]));           // d^CL
    int base = b * CH * C + c;

    float skv = 0.f, sk = 0.f;
#pragma unroll
    for (int ch = 0; ch < CH; ch++) {
        int ai = base + ch * C;
        iFkv[ai] = skv; iFk[ai] = sk;
        skv = skv * D + aFkv[ai];
        sk  = sk  * D + aFk[ai];
    }
    skv = 0.f; sk = 0.f;
#pragma unroll
    for (int ch = CH - 1; ch >= 0; ch--) {
        int ai = base + ch * C;
        iBkv[ai] = skv; iBk[ai] = sk;
        skv = skv * D + aBkv[ai];
        sk  = sk  * D + aBk[ai];
    }
}

__global__ __launch_bounds__(256) void wkv_apply_k(
    const float* __restrict__ r, const float* __restrict__ k,
    const float* __restrict__ v, const float* __restrict__ w,
    const float* __restrict__ u,
    const float* __restrict__ iFkv, const float* __restrict__ iFk,
    const float* __restrict__ iBkv, const float* __restrict__ iBk,
    __nv_bfloat16* __restrict__ y_hi, __nv_bfloat16* __restrict__ y_lo,
    float* __restrict__ sakv, float* __restrict__ sak) {
    int gid = blockIdx.x * blockDim.x + threadIdx.x;   // 0 .. B*CH*C-1
    int c = gid & (C - 1);
    int ch = (gid >> 10) & (CH - 1);
    int b = gid >> 14;
    float d = expf(-expf(w[c]));
    float eu = expf(u[c]);
    size_t base = (size_t)b * T * C + (size_t)ch * CL * C + c;

    float fkv = iFkv[gid], fk = iFk[gid];
#pragma unroll 4
    for (int i = 0; i < CL; i++) {
        size_t o = base + (size_t)i * C;
        float ek = expf(k[o]);
        float kv = ek * v[o];
        sakv[o] = fkv;
        sak[o]  = fk;
        fkv = fkv * d + kv;
        fk  = fk  * d + ek;
    }
    float bkv = iBkv[gid], bk = iBk[gid];
#pragma unroll 4
    for (int i = CL - 1; i >= 0; i--) {
        size_t o = base + (size_t)i * C;
        float vv = v[o];
        float ek = expf(k[o]);
        float kv = ek * vv;
        float num = sakv[o] + bkv + eu * vv;
        float den = sak[o]  + bk  + eu;
        float yv = r[o] * num / (den + 1e-8f);
        __nv_bfloat16 h = __float2bfloat16(yv);
        y_hi[o] = h;
        y_lo[o] = __float2bfloat16(yv - __bfloat162float(h));
        bkv = bkv * d + kv;
        bk  = bk  * d + ek;
    }
}

// ---------------------------------------------------------------------------
// Host launch
// ---------------------------------------------------------------------------
extern "C" void kernel_launch(void* const* d_in, const int* in_sizes, int n_in,
                              void* d_out, int out_size) {
    const int*   idx     = (const int*)  d_in[0];
    const float* emb     = (const float*)d_in[1];
    const float* ln1_w   = (const float*)d_in[2];
    const float* ln1_b   = (const float*)d_in[3];
    const float* Wr      = (const float*)d_in[4];
    const float* Wk      = (const float*)d_in[5];
    const float* Wv      = (const float*)d_in[6];
    const float* w_decay = (const float*)d_in[7];
    const float* u_bonus = (const float*)d_in[8];
    const float* Wo      = (const float*)d_in[9];
    const float* ln2_w   = (const float*)d_in[10];
    const float* ln2_b   = (const float*)d_in[11];
    const float* Wfk     = (const float*)d_in[12];
    const float* Wfv     = (const float*)d_in[13];
    const float* Wfr     = (const float*)d_in[14];
    const float* lnout_w = (const float*)d_in[15];
    const float* lnout_b = (const float*)d_in[16];
    const float* head_W  = (const float*)d_in[17];
    float* out = (float*)d_out;

    float *x, *r, *k, *v, *sa, *sb;
    float *aFkv, *aFk, *aBkv, *aBk, *iFkv, *iFk, *iBkv, *iBk;
    __nv_bfloat16 *wth, *wtl, *xnh, *xnl, *yh, *yl, *kfh, *kfl;
    cudaGetSymbolAddress((void**)&x,    g_x);
    cudaGetSymbolAddress((void**)&r,    g_r);
    cudaGetSymbolAddress((void**)&k,    g_k);
    cudaGetSymbolAddress((void**)&v,    g_v);
    cudaGetSymbolAddress((void**)&sa,   g_sakv);
    cudaGetSymbolAddress((void**)&sb,   g_sak);
    cudaGetSymbolAddress((void**)&wth,  g_wt_hi);
    cudaGetSymbolAddress((void**)&wtl,  g_wt_lo);
    cudaGetSymbolAddress((void**)&xnh,  g_xn_hi);
    cudaGetSymbolAddress((void**)&xnl,  g_xn_lo);
    cudaGetSymbolAddress((void**)&yh,   g_y_hi);
    cudaGetSymbolAddress((void**)&yl,   g_y_lo);
    cudaGetSymbolAddress((void**)&kfh,  g_kf_hi);
    cudaGetSymbolAddress((void**)&kfl,  g_kf_lo);
    cudaGetSymbolAddress((void**)&aFkv, g_aggFkv);
    cudaGetSymbolAddress((void**)&aFk,  g_aggFk);
    cudaGetSymbolAddress((void**)&aBkv, g_aggBkv);
    cudaGetSymbolAddress((void**)&aBk,  g_aggBk);
    cudaGetSymbolAddress((void**)&iFkv, g_iniFkv);
    cudaGetSymbolAddress((void**)&iFk,  g_iniFk);
    cudaGetSymbolAddress((void**)&iBkv, g_iniBkv);
    cudaGetSymbolAddress((void**)&iBk,  g_iniBk);

    cudaFuncSetAttribute(gemm_mma<0>, cudaFuncAttributeMaxDynamicSharedMemorySize, GEMM_SMEM);
    cudaFuncSetAttribute(gemm_mma<1>, cudaFuncAttributeMaxDynamicSharedMemorySize, GEMM_SMEM);
    cudaFuncSetAttribute(gemm_mma<2>, cudaFuncAttributeMaxDynamicSharedMemorySize, GEMM_SMEM);
    cudaFuncSetAttribute(gemm_mma<3>, cudaFuncAttributeMaxDynamicSharedMemorySize, GEMM_SMEM);
    cudaFuncSetAttribute(gemm_mma<4>, cudaFuncAttributeMaxDynamicSharedMemorySize, GEMM_SMEM);

    convert_all_k<<<4096, 256>>>((const float4*)Wr, (const float4*)Wk,
                                 (const float4*)Wv, (const float4*)Wo,
                                 (const float4*)Wfr, (const float4*)Wfk,
                                 (const float4*)Wfv, (const float4*)head_W,
                                 (uint2*)wth, (uint2*)wtl);

    embed_k<<<M, 256>>>(idx, emb, x);

    dim3 gCCg(M / 128, C / 128);
    dim3 gCFg(M / 128, F / 128);
    dim3 gCVg(M / 128, V / 128);

    for (int l = 0; l < L; l++) {
        size_t wcc = (size_t)l * C * C;
        size_t wcf = (size_t)l * C * F;
        const float* l1w = ln1_w + (size_t)l * C;
        const float* l1b = ln1_b + (size_t)l * C;
        const float* wd  = w_decay + (size_t)l * C;
        const float* ub  = u_bonus + (size_t)l * C;
        const float* l2w = ln2_w + (size_t)l * C;
        const float* l2b = ln2_b + (size_t)l * C;

        // time-mix
        layernorm_k<<<M, 256>>>(x, l1w, l1b, xnh, xnl);
        gemm_mma<1><<<gCCg, GTHREADS, GEMM_SMEM>>>(xnh, xnl, wth + O_WR + wcc, wtl + O_WR + wcc,
                                                   r, nullptr, nullptr, nullptr, nullptr, C, C);
        gemm_mma<0><<<gCCg, GTHREADS, GEMM_SMEM>>>(xnh, xnl, wth + O_WK + wcc, wtl + O_WK + wcc,
                                                   k, nullptr, nullptr, nullptr, nullptr, C, C);
        gemm_mma<0><<<gCCg, GTHREADS, GEMM_SMEM>>>(xnh, xnl, wth + O_WV + wcc, wtl + O_WV + wcc,
                                                   v, nullptr, nullptr, nullptr, nullptr, C, C);
        wkv_agg_k<<<(B * CH * C) / 256, 256>>>(k, v, wd, aFkv, aFk, aBkv, aBk);
        wkv_scan_k<<<(B * C) / 256, 256>>>(wd, aFkv, aFk, aBkv, aBk,
                                           iFkv, iFk, iBkv, iBk);
        wkv_apply_k<<<(B * CH * C) / 256, 256>>>(r, k, v, wd, ub,
                                                 iFkv, iFk, iBkv, iBk,
                                                 yh, yl, sa, sb);
        gemm_mma<3><<<gCCg, GTHREADS, GEMM_SMEM>>>(yh, yl, wth + O_WO + wcc, wtl + O_WO + wcc,
                                                   x, nullptr, nullptr, x, nullptr, C, C);

        // channel-mix
        layernorm_k<<<M, 256>>>(x, l2w, l2b, xnh, xnl);
        gemm_mma<1><<<gCCg, GTHREADS, GEMM_SMEM>>>(xnh, xnl, wth + O_WFR + wcc, wtl + O_WFR + wcc,
                                                   r, nullptr, nullptr, nullptr, nullptr, C, C);
        gemm_mma<2><<<gCFg, GTHREADS, GEMM_SMEM>>>(xnh, xnl, wth + O_WFK + wcf, wtl + O_WFK + wcf,
                                                   nullptr, kfh, kfl, nullptr, nullptr, F, C);
        gemm_mma<4><<<gCCg, GTHREADS, GEMM_SMEM>>>(kfh, kfl, wth + O_WFV + wcf, wtl + O_WFV + wcf,
                                                   x, nullptr, nullptr, x, r, C, F);
    }

    layernorm_k<<<M, 256>>>(x, lnout_w, lnout_b, xnh, xnl);
    gemm_mma<0><<<gCVg, GTHREADS, GEMM_SMEM>>>(xnh, xnl, wth + O_HEAD, wtl + O_HEAD,
                                               out, nullptr, nullptr, nullptr, nullptr, V, C);
}